// round 1
// baseline (speedup 1.0000x reference)
#include <cuda_runtime.h>
#include <math.h>

// ---------------- problem constants ----------------
#define Hc   1024
#define Lc   4096
#define Bc   8
#define Mtok (Bc * Lc)          // 32768 tokens

// ---------------- scratch (device globals; no allocs allowed) ----------------
__device__ float g_Wc[4 * Hc * Hc];            // conv weights transposed: [(k*H+hi)][ho]
__device__ float g_cnn[(size_t)Mtok * Hc];     // conv output (+bias), [b][l][h]
__device__ float g_xn[(size_t)Mtok * Hc];      // layernorm(cnn)
__device__ float g_U[(size_t)Mtok * 3 * Hc];   // xn @ sru_W
__device__ float g_blend[(size_t)Mtok * Hc];   // lambda*cnn + (1-lambda)*h
__device__ float g_gated[(size_t)Mtok * Hc];   // rmsnorm(blend)*x   (residual)
__device__ float g_a1[(size_t)Mtok * Hc];      // gelu(ln1(gated))
__device__ float g_t1[(size_t)Mtok * 2 * Hc];  // a1 @ lin1_w
__device__ float g_a2[(size_t)Mtok * 2 * Hc];  // gelu(ln2(t1))

// ---------------- helpers ----------------
__device__ __forceinline__ float blockReduceSum(float v) {
    __shared__ float red[32];
    int lane = threadIdx.x & 31;
    int wid  = threadIdx.x >> 5;
    #pragma unroll
    for (int o = 16; o > 0; o >>= 1) v += __shfl_xor_sync(0xffffffffu, v, o);
    if (lane == 0) red[wid] = v;
    __syncthreads();
    int nw = blockDim.x >> 5;
    if (wid == 0) {
        float s = (lane < nw) ? red[lane] : 0.0f;
        #pragma unroll
        for (int o = 16; o > 0; o >>= 1) s += __shfl_xor_sync(0xffffffffu, s, o);
        if (lane == 0) red[0] = s;
    }
    __syncthreads();
    float r = red[0];
    __syncthreads();
    return r;
}

__device__ __forceinline__ float geluf(float x) {
    return 0.5f * x * (1.0f + erff(x * 0.7071067811865476f));
}

// ---------------- conv weight transpose: (ho,hi,k) -> (k*H+hi, ho) ----------------
__global__ void transpose_convw_kernel(const float* __restrict__ w, float* __restrict__ wc) {
    int ho = blockIdx.x * 256 + threadIdx.x;   // grid.x = H/256
    int hi = blockIdx.y;                       // grid.y = H
    float4 v = *reinterpret_cast<const float4*>(w + ((size_t)ho * Hc + hi) * 4);
    wc[((size_t)0 * Hc + hi) * Hc + ho] = v.x;
    wc[((size_t)1 * Hc + hi) * Hc + ho] = v.y;
    wc[((size_t)2 * Hc + hi) * Hc + ho] = v.z;
    wc[((size_t)3 * Hc + hi) * Hc + ho] = v.w;
}

// ---------------- generic fp32 GEMM, 128x128x8, double-buffered ----------------
// CONV=1: A is x (B,L,H); logical A(t, c) = x[t + (c>>10) - 3][c&1023], causally masked.
template<int CONV>
__global__ void __launch_bounds__(256, 2)
sgemm_kernel(const float* __restrict__ A, const float* __restrict__ Bm,
             float* __restrict__ C,
             const float* __restrict__ bias,   // nullable, [N]
             const float* __restrict__ resid,  // nullable, [M][N]
             int N, int Kd)
{
    constexpr int BM = 128, BN = 128, BK = 8;
    __shared__ __align__(16) float As[2][BK * BM];  // transposed: As[k][m]
    __shared__ __align__(16) float Bs[2][BK * BN];  // Bs[k][n]

    const int tid = threadIdx.x;
    const int m0 = blockIdx.y * BM;
    const int n0 = blockIdx.x * BN;
    const int tx = tid & 15;         // 0..15 (cols)
    const int ty = tid >> 4;         // 0..15 (rows)
    const int aRow = tid >> 1;       // 0..127
    const int aCol = (tid & 1) * 4;  // 0 or 4
    const int bRow = tid >> 5;       // 0..7
    const int bCol = (tid & 31) * 4; // 0..124

    float acc[8][8];
    #pragma unroll
    for (int i = 0; i < 8; i++)
        #pragma unroll
        for (int j = 0; j < 8; j++) acc[i][j] = 0.0f;

    float4 aReg, bReg;

    // ---- tile load helpers (macros avoid lambda overhead) ----
    #define LOAD_A(kt, dst)                                                         \
        {                                                                           \
            int grow = m0 + aRow;                                                   \
            int gk = (kt) + aCol;                                                   \
            if (CONV) {                                                             \
                int kidx = gk >> 10;                                                \
                int hi = gk & 1023;                                                 \
                int lmod = grow & (Lc - 1);                                         \
                if (lmod + kidx >= 3) {                                             \
                    dst = *reinterpret_cast<const float4*>(                         \
                        A + (size_t)(grow + kidx - 3) * Hc + hi);                   \
                } else dst = make_float4(0.f, 0.f, 0.f, 0.f);                       \
            } else {                                                                \
                dst = *reinterpret_cast<const float4*>(A + (size_t)grow * Kd + gk); \
            }                                                                       \
        }
    #define LOAD_B(kt, dst)                                                         \
        dst = *reinterpret_cast<const float4*>(Bm + (size_t)((kt) + bRow) * N + n0 + bCol);
    #define STORE_AS(buf, v)                      \
        {                                         \
            As[buf][(aCol + 0) * BM + aRow] = v.x;\
            As[buf][(aCol + 1) * BM + aRow] = v.y;\
            As[buf][(aCol + 2) * BM + aRow] = v.z;\
            As[buf][(aCol + 3) * BM + aRow] = v.w;\
        }
    #define STORE_BS(buf, v)                                                        \
        *reinterpret_cast<float4*>(&Bs[buf][bRow * BN + bCol]) = v;

    // prologue
    LOAD_A(0, aReg); LOAD_B(0, bReg);
    STORE_AS(0, aReg); STORE_BS(0, bReg);
    __syncthreads();

    int buf = 0;
    const int T = Kd / BK;
    for (int t = 0; t < T; ++t) {
        if (t + 1 < T) {
            int ktn = (t + 1) * BK;
            LOAD_A(ktn, aReg); LOAD_B(ktn, bReg);
        }
        #pragma unroll
        for (int kk = 0; kk < BK; ++kk) {
            const float* ap = &As[buf][kk * BM + ty * 8];
            const float* bp = &Bs[buf][kk * BN + tx * 8];
            float4 a0 = *reinterpret_cast<const float4*>(ap);
            float4 a1 = *reinterpret_cast<const float4*>(ap + 4);
            float4 b0 = *reinterpret_cast<const float4*>(bp);
            float4 b1 = *reinterpret_cast<const float4*>(bp + 4);
            float ar[8] = {a0.x, a0.y, a0.z, a0.w, a1.x, a1.y, a1.z, a1.w};
            float br[8] = {b0.x, b0.y, b0.z, b0.w, b1.x, b1.y, b1.z, b1.w};
            #pragma unroll
            for (int i = 0; i < 8; i++)
                #pragma unroll
                for (int j = 0; j < 8; j++)
                    acc[i][j] = fmaf(ar[i], br[j], acc[i][j]);
        }
        if (t + 1 < T) {
            buf ^= 1;
            STORE_AS(buf, aReg); STORE_BS(buf, bReg);
            __syncthreads();
        }
    }

    // epilogue
    #pragma unroll
    for (int i = 0; i < 8; i++) {
        size_t row = (size_t)(m0 + ty * 8 + i);
        float* cr = C + row * N + n0 + tx * 8;
        #pragma unroll
        for (int j4 = 0; j4 < 8; j4 += 4) {
            float4 v = make_float4(acc[i][j4], acc[i][j4 + 1], acc[i][j4 + 2], acc[i][j4 + 3]);
            if (bias) {
                float4 bb = *reinterpret_cast<const float4*>(bias + n0 + tx * 8 + j4);
                v.x += bb.x; v.y += bb.y; v.z += bb.z; v.w += bb.w;
            }
            if (resid) {
                float4 rv = *reinterpret_cast<const float4*>(resid + row * N + n0 + tx * 8 + j4);
                v.x += rv.x; v.y += rv.y; v.z += rv.z; v.w += rv.w;
            }
            *reinterpret_cast<float4*>(cr + j4) = v;
        }
    }
    #undef LOAD_A
    #undef LOAD_B
    #undef STORE_AS
    #undef STORE_BS
}

// ---------------- layernorm over H=1024 (for SRU input) ----------------
__global__ void ln_kernel(const float* __restrict__ in, float* __restrict__ out,
                          const float* __restrict__ w, const float* __restrict__ b) {
    int t = blockIdx.x, tid = threadIdx.x;  // 256 threads
    const float* row = in + (size_t)t * Hc;
    float v[4];
    float s = 0.0f;
    #pragma unroll
    for (int i = 0; i < 4; i++) { v[i] = row[tid + i * 256]; s += v[i]; }
    s = blockReduceSum(s);
    float mean = s * (1.0f / Hc);
    float sq = 0.0f;
    #pragma unroll
    for (int i = 0; i < 4; i++) { float d = v[i] - mean; sq += d * d; }
    sq = blockReduceSum(sq);
    float rstd = rsqrtf(sq * (1.0f / Hc) + 1e-5f);
    #pragma unroll
    for (int i = 0; i < 4; i++) {
        int idx = tid + i * 256;
        out[(size_t)t * Hc + idx] = (v[i] - mean) * rstd * w[idx] + b[idx];
    }
}

// ---------------- SRU sequential scan + lambda blend ----------------
__global__ void scan_kernel(const float* __restrict__ U, const float* __restrict__ xn,
                            const float* __restrict__ cnn, float* __restrict__ blend,
                            const float* __restrict__ vf_, const float* __restrict__ vr_,
                            const float* __restrict__ bf_, const float* __restrict__ br_,
                            const float* __restrict__ lam_, int Bv) {
    int g = blockIdx.x * blockDim.x + threadIdx.x;
    if (g >= Bv * Hc) return;
    int b = g >> 10, h = g & 1023;
    const float vf = vf_[h], vr = vr_[h], bfv = bf_[h], brv = br_[h], lam = lam_[h];
    const float SCALE_X = sqrtf(1.0f + expf(-4.0f));  // sqrt(1 + e^{2*bias}), bias=-2
    size_t iu = ((size_t)b * Lc) * (3 * Hc) + h;
    size_t ix = ((size_t)b * Lc) * Hc + h;
    float c = 0.0f;
    #pragma unroll 2
    for (int l = 0; l < Lc; ++l) {
        float u0 = U[iu], u1 = U[iu + Hc], u2 = U[iu + 2 * Hc];
        float xr = xn[ix] * SCALE_X;
        float cnv = cnn[ix];
        float f = 1.0f / (1.0f + __expf(-(fmaf(c, vf, u1) + bfv)));
        float cn = fmaf(f, c - u0, u0);                     // f*c + (1-f)*u0
        float r = 1.0f / (1.0f + __expf(-(fmaf(c, vr, u2) + brv)));
        float th = tanhf(cn);
        float ht = fmaf(r, th - xr, xr);                    // r*tanh + (1-r)*xr
        blend[ix] = fmaf(lam, cnv - ht, ht);                // lam*cnn + (1-lam)*h
        c = cn;
        iu += 3 * Hc;
        ix += Hc;
    }
}

// ---------------- rmsnorm + input gate + ln1 + gelu (fused, per token) ----------------
__global__ void rms_gate_ln1_kernel(const float* __restrict__ blend, const float* __restrict__ x,
                                    const float* __restrict__ rmsw,
                                    const float* __restrict__ ln1w, const float* __restrict__ ln1b,
                                    float* __restrict__ gated, float* __restrict__ a1) {
    int t = blockIdx.x, tid = threadIdx.x;
    size_t base = (size_t)t * Hc;
    float v[4], g[4];
    float sq = 0.0f;
    #pragma unroll
    for (int i = 0; i < 4; i++) { v[i] = blend[base + tid + i * 256]; sq += v[i] * v[i]; }
    sq = blockReduceSum(sq);
    float rs = rsqrtf(sq * (1.0f / Hc) + 1e-6f);
    float s = 0.0f;
    #pragma unroll
    for (int i = 0; i < 4; i++) {
        int idx = tid + i * 256;
        float o = rmsw[idx] * v[i] * rs;
        g[i] = o * x[base + idx];
        gated[base + idx] = g[i];
        s += g[i];
    }
    s = blockReduceSum(s);
    float mean = s * (1.0f / Hc);
    float var = 0.0f;
    #pragma unroll
    for (int i = 0; i < 4; i++) { float d = g[i] - mean; var += d * d; }
    var = blockReduceSum(var);
    float rstd = rsqrtf(var * (1.0f / Hc) + 1e-5f);
    #pragma unroll
    for (int i = 0; i < 4; i++) {
        int idx = tid + i * 256;
        a1[base + idx] = geluf((g[i] - mean) * rstd * ln1w[idx] + ln1b[idx]);
    }
}

// ---------------- ln2 + gelu over 2H (per token) ----------------
__global__ void ln2_gelu_kernel(const float* __restrict__ t1, float* __restrict__ a2,
                                const float* __restrict__ w, const float* __restrict__ b) {
    int t = blockIdx.x, tid = threadIdx.x;
    const int NN = 2 * Hc;
    size_t base = (size_t)t * NN;
    float v[8];
    float s = 0.0f;
    #pragma unroll
    for (int i = 0; i < 8; i++) { v[i] = t1[base + tid + i * 256]; s += v[i]; }
    s = blockReduceSum(s);
    float mean = s * (1.0f / NN);
    float sq = 0.0f;
    #pragma unroll
    for (int i = 0; i < 8; i++) { float d = v[i] - mean; sq += d * d; }
    sq = blockReduceSum(sq);
    float rstd = rsqrtf(sq * (1.0f / NN) + 1e-5f);
    #pragma unroll
    for (int i = 0; i < 8; i++) {
        int idx = tid + i * 256;
        a2[base + idx] = geluf((v[i] - mean) * rstd * w[idx] + b[idx]);
    }
}

// ---------------- launch ----------------
extern "C" void kernel_launch(void* const* d_in, const int* in_sizes, int n_in,
                              void* d_out, int out_size) {
    const float* x        = (const float*)d_in[0];
    const float* conv_w   = (const float*)d_in[1];
    const float* conv_b   = (const float*)d_in[2];
    const float* sru_ln_w = (const float*)d_in[3];
    const float* sru_ln_b = (const float*)d_in[4];
    const float* sru_W    = (const float*)d_in[5];
    const float* sru_vf   = (const float*)d_in[6];
    const float* sru_vr   = (const float*)d_in[7];
    const float* sru_bf   = (const float*)d_in[8];
    const float* sru_br   = (const float*)d_in[9];
    const float* lambda_w = (const float*)d_in[10];
    const float* rms_w    = (const float*)d_in[11];
    const float* ln1_w    = (const float*)d_in[12];
    const float* ln1_b    = (const float*)d_in[13];
    const float* lin1_w   = (const float*)d_in[14];
    const float* ln2_w    = (const float*)d_in[15];
    const float* ln2_b    = (const float*)d_in[16];
    const float* lin2_w   = (const float*)d_in[17];
    const float* lin2_b   = (const float*)d_in[18];

    int Bv = in_sizes[0] / (Lc * Hc);   // expect 8
    int M  = Bv * Lc;                   // 32768

    float *Wc, *cnn, *xn, *U, *blend, *gated, *a1, *t1, *a2;
    cudaGetSymbolAddress((void**)&Wc,    g_Wc);
    cudaGetSymbolAddress((void**)&cnn,   g_cnn);
    cudaGetSymbolAddress((void**)&xn,    g_xn);
    cudaGetSymbolAddress((void**)&U,     g_U);
    cudaGetSymbolAddress((void**)&blend, g_blend);
    cudaGetSymbolAddress((void**)&gated, g_gated);
    cudaGetSymbolAddress((void**)&a1,    g_a1);
    cudaGetSymbolAddress((void**)&t1,    g_t1);
    cudaGetSymbolAddress((void**)&a2,    g_a2);

    // 1. transpose conv weights -> Wc[(k*H+hi)][ho]
    transpose_convw_kernel<<<dim3(Hc / 256, Hc), 256>>>(conv_w, Wc);

    // 2. causal conv as GEMM: cnn = im2col(x) @ Wc + conv_b
    sgemm_kernel<1><<<dim3(Hc / 128, M / 128), 256>>>(x, Wc, cnn, conv_b, nullptr, Hc, 4 * Hc);

    // 3. layernorm(cnn) -> xn
    ln_kernel<<<M, 256>>>(cnn, xn, sru_ln_w, sru_ln_b);

    // 4. U = xn @ sru_W
    sgemm_kernel<0><<<dim3(3 * Hc / 128, M / 128), 256>>>(xn, sru_W, U, nullptr, nullptr, 3 * Hc, Hc);

    // 5. SRU scan + lambda blend -> blend
    scan_kernel<<<(Bv * Hc + 31) / 32, 32>>>(U, xn, cnn, blend,
                                             sru_vf, sru_vr, sru_bf, sru_br, lambda_w, Bv);

    // 6. rmsnorm + gate-by-x + ln1 + gelu  -> gated (residual), a1 (GEMM input)
    rms_gate_ln1_kernel<<<M, 256>>>(blend, x, rms_w, ln1_w, ln1_b, gated, a1);

    // 7. t1 = a1 @ lin1_w
    sgemm_kernel<0><<<dim3(2 * Hc / 128, M / 128), 256>>>(a1, lin1_w, t1, nullptr, nullptr, 2 * Hc, Hc);

    // 8. a2 = gelu(ln2(t1))
    ln2_gelu_kernel<<<M, 256>>>(t1, a2, ln2_w, ln2_b);

    // 9. out = a2 @ lin2_w + lin2_b + gated
    sgemm_kernel<0><<<dim3(Hc / 128, M / 128), 256>>>(a2, lin2_w, (float*)d_out, lin2_b, gated, Hc, 2 * Hc);
}

// round 3
// speedup vs baseline: 1.8656x; 1.8656x over previous
#include <cuda_runtime.h>
#include <cuda_bf16.h>
#include <math.h>
#include <stdint.h>

// ---------------- problem constants ----------------
#define Hc   1024
#define Lc   4096
#define Bc   8
#define Mtok (Bc * Lc)          // 32768 tokens

typedef __nv_bfloat16 bf16;

// ---------------- scratch (device globals; no allocs allowed) ----------------
__device__ float g_cnn[(size_t)Mtok * Hc];
__device__ float g_xn[(size_t)Mtok * Hc];
__device__ float g_U[(size_t)Mtok * 3 * Hc];
__device__ float g_blend[(size_t)Mtok * Hc];
__device__ float g_gated[(size_t)Mtok * Hc];
__device__ float g_t1[(size_t)Mtok * 2 * Hc];
// bf16 hi/lo activation copies
__device__ bf16 g_xh[(size_t)Mtok * Hc],      g_xl[(size_t)Mtok * Hc];
__device__ bf16 g_xnh[(size_t)Mtok * Hc],     g_xnl[(size_t)Mtok * Hc];
__device__ bf16 g_a1h[(size_t)Mtok * Hc],     g_a1l[(size_t)Mtok * Hc];
__device__ bf16 g_a2h[(size_t)Mtok * 2 * Hc], g_a2l[(size_t)Mtok * 2 * Hc];
// transposed bf16 split weights, layout [N][K]
__device__ bf16 g_WcT_hi[1024 * 4096], g_WcT_lo[1024 * 4096];
__device__ bf16 g_WuT_hi[3072 * 1024], g_WuT_lo[3072 * 1024];
__device__ bf16 g_W1T_hi[2048 * 1024], g_W1T_lo[2048 * 1024];
__device__ bf16 g_W2T_hi[1024 * 2048], g_W2T_lo[1024 * 2048];

// ---------------- helpers ----------------
__device__ __forceinline__ float blockReduceSum(float v) {
    __shared__ float red[32];
    int lane = threadIdx.x & 31;
    int wid  = threadIdx.x >> 5;
    #pragma unroll
    for (int o = 16; o > 0; o >>= 1) v += __shfl_xor_sync(0xffffffffu, v, o);
    if (lane == 0) red[wid] = v;
    __syncthreads();
    int nw = blockDim.x >> 5;
    if (wid == 0) {
        float s = (lane < nw) ? red[lane] : 0.0f;
        #pragma unroll
        for (int o = 16; o > 0; o >>= 1) s += __shfl_xor_sync(0xffffffffu, s, o);
        if (lane == 0) red[0] = s;
    }
    __syncthreads();
    float r = red[0];
    __syncthreads();
    return r;
}

__device__ __forceinline__ float geluf(float x) {
    return 0.5f * x * (1.0f + erff(x * 0.7071067811865476f));
}

__device__ __forceinline__ void split1(float v, bf16& h, bf16& l) {
    h = __float2bfloat16(v);
    l = __float2bfloat16(v - __bfloat162float(h));
}

// ---------------- weight prep ----------------
// fp32 [K][N] row-major -> bf16 hi/lo [N][K]
__global__ void wtrans_kernel(const float* __restrict__ in,
                              bf16* __restrict__ oh, bf16* __restrict__ ol,
                              int Kd, int N) {
    __shared__ float tile[32][33];
    int n0 = blockIdx.x * 32, k0 = blockIdx.y * 32;
    int tx = threadIdx.x, ty = threadIdx.y;  // 32 x 8
    #pragma unroll
    for (int i = 0; i < 32; i += 8)
        tile[ty + i][tx] = in[(size_t)(k0 + ty + i) * N + n0 + tx];
    __syncthreads();
    #pragma unroll
    for (int i = 0; i < 32; i += 8) {
        float v = tile[tx][ty + i];
        size_t o = (size_t)(n0 + ty + i) * Kd + k0 + tx;
        bf16 h, l; split1(v, h, l);
        oh[o] = h; ol[o] = l;
    }
}

// conv weights (ho,hi,k) -> [ho][k*1024+hi]
__global__ void wconv_kernel(const float* __restrict__ w,
                             bf16* __restrict__ oh, bf16* __restrict__ ol) {
    int ho = blockIdx.x;
    for (int hi = threadIdx.x; hi < 1024; hi += 256) {
        float4 v = *reinterpret_cast<const float4*>(w + ((size_t)ho * 1024 + hi) * 4);
        float vv[4] = {v.x, v.y, v.z, v.w};
        #pragma unroll
        for (int k = 0; k < 4; k++) {
            size_t o = (size_t)ho * 4096 + k * 1024 + hi;
            bf16 h, l; split1(vv[k], h, l);
            oh[o] = h; ol[o] = l;
        }
    }
}

// fp32 -> bf16 hi/lo elementwise
__global__ void fcvt_kernel(const float* __restrict__ in,
                            bf16* __restrict__ oh, bf16* __restrict__ ol) {
    size_t i = ((size_t)blockIdx.x * 256 + threadIdx.x) * 4;
    float4 v = *reinterpret_cast<const float4*>(in + i);
    bf16 h, l;
    split1(v.x, h, l); oh[i] = h;     ol[i] = l;
    split1(v.y, h, l); oh[i + 1] = h; ol[i + 1] = l;
    split1(v.z, h, l); oh[i + 2] = h; ol[i + 2] = l;
    split1(v.w, h, l); oh[i + 3] = h; ol[i + 3] = l;
}

// ---------------- HMMA bf16x3 GEMM ----------------
// C[M,N] = A @ B(+bias)(+resid), A/B given as bf16 hi/lo.
// A: [M][K] row-major (CONV=1: A(t, k*1024+hi) = x[t+k-3][hi], causal mask)
// B: [N][K] row-major (i.e. B^T, the "col" operand of mma.row.col)
#define ROWB 80                       // padded SMEM row stride (32 bf16 + 16B pad)
#define STG_BYTES (128 * ROWB)        // one tile region = 10240 B
#define BUF_BYTES (4 * STG_BYTES)     // Ahi|Alo|Bhi|Blo = 40960 B
#define SMEM_TOT (2 * BUF_BYTES)      // 81920 B

#define MMA16816(d, a, b)                                                        \
    asm volatile("mma.sync.aligned.m16n8k16.row.col.f32.bf16.bf16.f32 "          \
                 "{%0,%1,%2,%3},{%4,%5,%6,%7},{%8,%9},{%0,%1,%2,%3};"            \
                 : "+f"((d)[0]), "+f"((d)[1]), "+f"((d)[2]), "+f"((d)[3])        \
                 : "r"((a)[0]), "r"((a)[1]), "r"((a)[2]), "r"((a)[3]),           \
                   "r"((b)[0]), "r"((b)[1]))

template<int CONV>
__global__ void __launch_bounds__(256, 1)
mma_gemm(const bf16* __restrict__ Ahi, const bf16* __restrict__ Alo,
         const bf16* __restrict__ Bhi, const bf16* __restrict__ Blo,
         float* __restrict__ C,
         const float* __restrict__ bias, const float* __restrict__ resid,
         int N, int Kd)
{
    extern __shared__ char sm[];
    const int tid = threadIdx.x;
    const int wid = tid >> 5, lid = tid & 31;
    const int wm = wid >> 2, wn = wid & 3;         // 2 x 4 warp grid
    const int g = lid >> 2, t4 = lid & 3;
    const int m0 = blockIdx.y * 128, n0 = blockIdx.x * 128;

    float acc[4][4][4];
    #pragma unroll
    for (int i = 0; i < 4; i++)
        #pragma unroll
        for (int j = 0; j < 4; j++)
            #pragma unroll
            for (int q = 0; q < 4; q++) acc[i][j][q] = 0.0f;

    uint4 stg[8];  // staged global loads: Ahi[2], Alo[2], Bhi[2], Blo[2]

    // ---- global tile load: 512 chunks of 16B per region, 2 per thread ----
    #define LOADG(kg)                                                                  \
        {                                                                              \
            _Pragma("unroll")                                                          \
            for (int p = 0; p < 2; ++p) {                                              \
                int ch = p * 256 + tid;                                                \
                int row = ch >> 2, c = ch & 3;                                         \
                size_t boff = (size_t)(n0 + row) * Kd + (kg) + c * 8;                  \
                stg[4 + p] = *reinterpret_cast<const uint4*>(Bhi + boff);              \
                stg[6 + p] = *reinterpret_cast<const uint4*>(Blo + boff);              \
                if (CONV) {                                                            \
                    int kidx = (kg) >> 10;                                             \
                    bool ok = (((m0 + row) & (Lc - 1)) + kidx) >= 3;                   \
                    if (ok) {                                                          \
                        size_t aoff = (size_t)(m0 + row + kidx - 3) * Hc +             \
                                      ((kg) & 1023) + c * 8;                           \
                        stg[0 + p] = *reinterpret_cast<const uint4*>(Ahi + aoff);      \
                        stg[2 + p] = *reinterpret_cast<const uint4*>(Alo + aoff);      \
                    } else {                                                           \
                        stg[0 + p] = make_uint4(0, 0, 0, 0);                           \
                        stg[2 + p] = make_uint4(0, 0, 0, 0);                           \
                    }                                                                  \
                } else {                                                               \
                    size_t aoff = (size_t)(m0 + row) * Kd + (kg) + c * 8;              \
                    stg[0 + p] = *reinterpret_cast<const uint4*>(Ahi + aoff);          \
                    stg[2 + p] = *reinterpret_cast<const uint4*>(Alo + aoff);          \
                }                                                                      \
            }                                                                          \
        }

    #define STOREG(b)                                                                  \
        {                                                                              \
            char* base = sm + (b) * BUF_BYTES;                                         \
            _Pragma("unroll")                                                          \
            for (int p = 0; p < 2; ++p) {                                              \
                int ch = p * 256 + tid;                                                \
                int row = ch >> 2, c = ch & 3;                                         \
                uint32_t off = row * ROWB + c * 16;                                    \
                *reinterpret_cast<uint4*>(base + 0 * STG_BYTES + off) = stg[0 + p];    \
                *reinterpret_cast<uint4*>(base + 1 * STG_BYTES + off) = stg[2 + p];    \
                *reinterpret_cast<uint4*>(base + 2 * STG_BYTES + off) = stg[4 + p];    \
                *reinterpret_cast<uint4*>(base + 3 * STG_BYTES + off) = stg[6 + p];    \
            }                                                                          \
        }

    LOADG(0);
    STOREG(0);
    __syncthreads();

    const int T = Kd / 32;
    for (int t = 0; t < T; ++t) {
        if (t + 1 < T) LOADG((t + 1) * 32);

        const char* base = sm + (t & 1) * BUF_BYTES;
        const char* sAh = base;
        const char* sAl = base + STG_BYTES;
        const char* sBh = base + 2 * STG_BYTES;
        const char* sBl = base + 3 * STG_BYTES;

        #pragma unroll
        for (int ks = 0; ks < 2; ++ks) {
            const int kb = ks * 32 + t4 * 4;  // byte offset of this thread's k pair
            uint32_t afh[4][4], afl[4][4], bfh[4][2], bfl[4][2];
            #pragma unroll
            for (int i = 0; i < 4; ++i) {
                int r0 = (wm * 64 + i * 16 + g) * ROWB + kb;
                int r1 = r0 + 8 * ROWB;
                afh[i][0] = *reinterpret_cast<const uint32_t*>(sAh + r0);
                afh[i][1] = *reinterpret_cast<const uint32_t*>(sAh + r1);
                afh[i][2] = *reinterpret_cast<const uint32_t*>(sAh + r0 + 16);
                afh[i][3] = *reinterpret_cast<const uint32_t*>(sAh + r1 + 16);
                afl[i][0] = *reinterpret_cast<const uint32_t*>(sAl + r0);
                afl[i][1] = *reinterpret_cast<const uint32_t*>(sAl + r1);
                afl[i][2] = *reinterpret_cast<const uint32_t*>(sAl + r0 + 16);
                afl[i][3] = *reinterpret_cast<const uint32_t*>(sAl + r1 + 16);
            }
            #pragma unroll
            for (int j = 0; j < 4; ++j) {
                int rb = (wn * 32 + j * 8 + g) * ROWB + kb;
                bfh[j][0] = *reinterpret_cast<const uint32_t*>(sBh + rb);
                bfh[j][1] = *reinterpret_cast<const uint32_t*>(sBh + rb + 16);
                bfl[j][0] = *reinterpret_cast<const uint32_t*>(sBl + rb);
                bfl[j][1] = *reinterpret_cast<const uint32_t*>(sBl + rb + 16);
            }
            #pragma unroll
            for (int i = 0; i < 4; ++i)
                #pragma unroll
                for (int j = 0; j < 4; ++j) {
                    MMA16816(acc[i][j], afh[i], bfh[j]);
                    MMA16816(acc[i][j], afh[i], bfl[j]);
                    MMA16816(acc[i][j], afl[i], bfh[j]);
                }
        }

        if (t + 1 < T) {
            STOREG((t + 1) & 1);
        }
        __syncthreads();
    }

    // ---- epilogue ----
    #pragma unroll
    for (int i = 0; i < 4; ++i) {
        int r0 = m0 + wm * 64 + i * 16 + g;
        #pragma unroll
        for (int j = 0; j < 4; ++j) {
            int cc = n0 + wn * 32 + j * 8 + 2 * t4;
            float2 v0 = make_float2(acc[i][j][0], acc[i][j][1]);
            float2 v1 = make_float2(acc[i][j][2], acc[i][j][3]);
            if (bias) {
                float2 bb = *reinterpret_cast<const float2*>(bias + cc);
                v0.x += bb.x; v0.y += bb.y; v1.x += bb.x; v1.y += bb.y;
            }
            if (resid) {
                float2 q0 = *reinterpret_cast<const float2*>(resid + (size_t)r0 * N + cc);
                float2 q1 = *reinterpret_cast<const float2*>(resid + (size_t)(r0 + 8) * N + cc);
                v0.x += q0.x; v0.y += q0.y; v1.x += q1.x; v1.y += q1.y;
            }
            *reinterpret_cast<float2*>(C + (size_t)r0 * N + cc) = v0;
            *reinterpret_cast<float2*>(C + (size_t)(r0 + 8) * N + cc) = v1;
        }
    }
    #undef LOADG
    #undef STOREG
}

// ---------------- layernorm over H=1024 (+ bf16 hi/lo emit) ----------------
__global__ void ln_kernel(const float* __restrict__ in, float* __restrict__ out,
                          bf16* __restrict__ oh, bf16* __restrict__ ol,
                          const float* __restrict__ w, const float* __restrict__ b) {
    int t = blockIdx.x, tid = threadIdx.x;
    const float* row = in + (size_t)t * Hc;
    float v[4];
    float s = 0.0f;
    #pragma unroll
    for (int i = 0; i < 4; i++) { v[i] = row[tid + i * 256]; s += v[i]; }
    s = blockReduceSum(s);
    float mean = s * (1.0f / Hc);
    float sq = 0.0f;
    #pragma unroll
    for (int i = 0; i < 4; i++) { float d = v[i] - mean; sq += d * d; }
    sq = blockReduceSum(sq);
    float rstd = rsqrtf(sq * (1.0f / Hc) + 1e-5f);
    #pragma unroll
    for (int i = 0; i < 4; i++) {
        int idx = tid + i * 256;
        float o = (v[i] - mean) * rstd * w[idx] + b[idx];
        out[(size_t)t * Hc + idx] = o;
        bf16 h, l; split1(o, h, l);
        oh[(size_t)t * Hc + idx] = h;
        ol[(size_t)t * Hc + idx] = l;
    }
}

// ---------------- SRU scan + lambda blend ----------------
__global__ void scan_kernel(const float* __restrict__ U, const float* __restrict__ xn,
                            const float* __restrict__ cnn, float* __restrict__ blend,
                            const float* __restrict__ vf_, const float* __restrict__ vr_,
                            const float* __restrict__ bf_, const float* __restrict__ br_,
                            const float* __restrict__ lam_, int Bv) {
    int g = blockIdx.x * blockDim.x + threadIdx.x;
    if (g >= Bv * Hc) return;
    int b = g >> 10, h = g & 1023;
    const float vf = vf_[h], vr = vr_[h], bfv = bf_[h], brv = br_[h], lam = lam_[h];
    const float SCALE_X = sqrtf(1.0f + expf(-4.0f));
    size_t iu = ((size_t)b * Lc) * (3 * Hc) + h;
    size_t ix = ((size_t)b * Lc) * Hc + h;
    float c = 0.0f;
    #pragma unroll 2
    for (int l = 0; l < Lc; ++l) {
        float u0 = U[iu], u1 = U[iu + Hc], u2 = U[iu + 2 * Hc];
        float xr = xn[ix] * SCALE_X;
        float cnv = cnn[ix];
        float f = 1.0f / (1.0f + __expf(-(fmaf(c, vf, u1) + bfv)));
        float cn = fmaf(f, c - u0, u0);
        float r = 1.0f / (1.0f + __expf(-(fmaf(c, vr, u2) + brv)));
        float th = tanhf(cn);
        float ht = fmaf(r, th - xr, xr);
        blend[ix] = fmaf(lam, cnv - ht, ht);
        c = cn;
        iu += 3 * Hc;
        ix += Hc;
    }
}

// ---------------- rmsnorm + gate + ln1 + gelu -> gated(f32), a1 hi/lo ----------------
__global__ void rms_gate_ln1_kernel(const float* __restrict__ blend, const float* __restrict__ x,
                                    const float* __restrict__ rmsw,
                                    const float* __restrict__ ln1w, const float* __restrict__ ln1b,
                                    float* __restrict__ gated,
                                    bf16* __restrict__ a1h, bf16* __restrict__ a1l) {
    int t = blockIdx.x, tid = threadIdx.x;
    size_t base = (size_t)t * Hc;
    float v[4], g[4];
    float sq = 0.0f;
    #pragma unroll
    for (int i = 0; i < 4; i++) { v[i] = blend[base + tid + i * 256]; sq += v[i] * v[i]; }
    sq = blockReduceSum(sq);
    float rs = rsqrtf(sq * (1.0f / Hc) + 1e-6f);
    float s = 0.0f;
    #pragma unroll
    for (int i = 0; i < 4; i++) {
        int idx = tid + i * 256;
        float o = rmsw[idx] * v[i] * rs;
        g[i] = o * x[base + idx];
        gated[base + idx] = g[i];
        s += g[i];
    }
    s = blockReduceSum(s);
    float mean = s * (1.0f / Hc);
    float var = 0.0f;
    #pragma unroll
    for (int i = 0; i < 4; i++) { float d = g[i] - mean; var += d * d; }
    var = blockReduceSum(var);
    float rstd = rsqrtf(var * (1.0f / Hc) + 1e-5f);
    #pragma unroll
    for (int i = 0; i < 4; i++) {
        int idx = tid + i * 256;
        float a = geluf((g[i] - mean) * rstd * ln1w[idx] + ln1b[idx]);
        bf16 h, l; split1(a, h, l);
        a1h[base + idx] = h;
        a1l[base + idx] = l;
    }
}

// ---------------- ln2 + gelu over 2H -> a2 hi/lo ----------------
__global__ void ln2_gelu_kernel(const float* __restrict__ t1,
                                bf16* __restrict__ a2h, bf16* __restrict__ a2l,
                                const float* __restrict__ w, const float* __restrict__ b) {
    int t = blockIdx.x, tid = threadIdx.x;
    const int NN = 2 * Hc;
    size_t base = (size_t)t * NN;
    float v[8];
    float s = 0.0f;
    #pragma unroll
    for (int i = 0; i < 8; i++) { v[i] = t1[base + tid + i * 256]; s += v[i]; }
    s = blockReduceSum(s);
    float mean = s * (1.0f / NN);
    float sq = 0.0f;
    #pragma unroll
    for (int i = 0; i < 8; i++) { float d = v[i] - mean; sq += d * d; }
    sq = blockReduceSum(sq);
    float rstd = rsqrtf(sq * (1.0f / NN) + 1e-5f);
    #pragma unroll
    for (int i = 0; i < 8; i++) {
        int idx = tid + i * 256;
        float a = geluf((v[i] - mean) * rstd * w[idx] + b[idx]);
        bf16 h, l; split1(a, h, l);
        a2h[base + idx] = h;
        a2l[base + idx] = l;
    }
}

// ---------------- launch ----------------
extern "C" void kernel_launch(void* const* d_in, const int* in_sizes, int n_in,
                              void* d_out, int out_size) {
    const float* x        = (const float*)d_in[0];
    const float* conv_w   = (const float*)d_in[1];
    const float* conv_b   = (const float*)d_in[2];
    const float* sru_ln_w = (const float*)d_in[3];
    const float* sru_ln_b = (const float*)d_in[4];
    const float* sru_W    = (const float*)d_in[5];
    const float* sru_vf   = (const float*)d_in[6];
    const float* sru_vr   = (const float*)d_in[7];
    const float* sru_bf   = (const float*)d_in[8];
    const float* sru_br   = (const float*)d_in[9];
    const float* lambda_w = (const float*)d_in[10];
    const float* rms_w    = (const float*)d_in[11];
    const float* ln1_w    = (const float*)d_in[12];
    const float* ln1_b    = (const float*)d_in[13];
    const float* lin1_w   = (const float*)d_in[14];
    const float* ln2_w    = (const float*)d_in[15];
    const float* ln2_b    = (const float*)d_in[16];
    const float* lin2_w   = (const float*)d_in[17];
    const float* lin2_b   = (const float*)d_in[18];

    int Bv = in_sizes[0] / (Lc * Hc);
    int M  = Bv * Lc;

    float *cnn, *xn, *U, *blend, *gated, *t1;
    bf16 *xh, *xl, *xnh, *xnl, *a1h, *a1l, *a2h, *a2l;
    bf16 *WcH, *WcL, *WuH, *WuL, *W1H, *W1L, *W2H, *W2L;
    cudaGetSymbolAddress((void**)&cnn,   g_cnn);
    cudaGetSymbolAddress((void**)&xn,    g_xn);
    cudaGetSymbolAddress((void**)&U,     g_U);
    cudaGetSymbolAddress((void**)&blend, g_blend);
    cudaGetSymbolAddress((void**)&gated, g_gated);
    cudaGetSymbolAddress((void**)&t1,    g_t1);
    cudaGetSymbolAddress((void**)&xh,  g_xh);  cudaGetSymbolAddress((void**)&xl,  g_xl);
    cudaGetSymbolAddress((void**)&xnh, g_xnh); cudaGetSymbolAddress((void**)&xnl, g_xnl);
    cudaGetSymbolAddress((void**)&a1h, g_a1h); cudaGetSymbolAddress((void**)&a1l, g_a1l);
    cudaGetSymbolAddress((void**)&a2h, g_a2h); cudaGetSymbolAddress((void**)&a2l, g_a2l);
    cudaGetSymbolAddress((void**)&WcH, g_WcT_hi); cudaGetSymbolAddress((void**)&WcL, g_WcT_lo);
    cudaGetSymbolAddress((void**)&WuH, g_WuT_hi); cudaGetSymbolAddress((void**)&WuL, g_WuT_lo);
    cudaGetSymbolAddress((void**)&W1H, g_W1T_hi); cudaGetSymbolAddress((void**)&W1L, g_W1T_lo);
    cudaGetSymbolAddress((void**)&W2H, g_W2T_hi); cudaGetSymbolAddress((void**)&W2L, g_W2T_lo);

    cudaFuncSetAttribute(mma_gemm<0>, cudaFuncAttributeMaxDynamicSharedMemorySize, SMEM_TOT);
    cudaFuncSetAttribute(mma_gemm<1>, cudaFuncAttributeMaxDynamicSharedMemorySize, SMEM_TOT);

    // weight + input prep
    wconv_kernel<<<1024, 256>>>(conv_w, WcH, WcL);
    wtrans_kernel<<<dim3(3072 / 32, 1024 / 32), dim3(32, 8)>>>(sru_W, WuH, WuL, 1024, 3072);
    wtrans_kernel<<<dim3(2048 / 32, 1024 / 32), dim3(32, 8)>>>(lin1_w, W1H, W1L, 1024, 2048);
    wtrans_kernel<<<dim3(1024 / 32, 2048 / 32), dim3(32, 8)>>>(lin2_w, W2H, W2L, 2048, 1024);
    fcvt_kernel<<<(size_t)M * Hc / 1024, 256>>>(x, xh, xl);

    // 1. causal conv as GEMM
    mma_gemm<1><<<dim3(Hc / 128, M / 128), 256, SMEM_TOT>>>(xh, xl, WcH, WcL, cnn, conv_b, nullptr, Hc, 4 * Hc);
    // 2. layernorm (+ bf16 split)
    ln_kernel<<<M, 256>>>(cnn, xn, xnh, xnl, sru_ln_w, sru_ln_b);
    // 3. U = xn @ sru_W
    mma_gemm<0><<<dim3(3 * Hc / 128, M / 128), 256, SMEM_TOT>>>(xnh, xnl, WuH, WuL, U, nullptr, nullptr, 3 * Hc, Hc);
    // 4. SRU scan + blend
    scan_kernel<<<(Bv * Hc + 127) / 128, 128>>>(U, xn, cnn, blend,
                                                sru_vf, sru_vr, sru_bf, sru_br, lambda_w, Bv);
    // 5. rmsnorm + gate + ln1 + gelu
    rms_gate_ln1_kernel<<<M, 256>>>(blend, x, rms_w, ln1_w, ln1_b, gated, a1h, a1l);
    // 6. t1 = a1 @ lin1_w
    mma_gemm<0><<<dim3(2 * Hc / 128, M / 128), 256, SMEM_TOT>>>(a1h, a1l, W1H, W1L, t1, nullptr, nullptr, 2 * Hc, Hc);
    // 7. a2 = gelu(ln2(t1))
    ln2_gelu_kernel<<<M, 256>>>(t1, a2h, a2l, ln2_w, ln2_b);
    // 8. out = a2 @ lin2_w + lin2_b + gated
    mma_gemm<0><<<dim3(Hc / 128, M / 128), 256, SMEM_TOT>>>(a2h, a2l, W2H, W2L, (float*)d_out, lin2_b, gated, Hc, 2 * Hc);
}

// round 4
// speedup vs baseline: 1.9882x; 1.0657x over previous
#include <cuda_runtime.h>
#include <cuda_bf16.h>
#include <math.h>
#include <stdint.h>

// ---------------- problem constants ----------------
#define Hc   1024
#define Lc   4096
#define Bc   8
#define Mtok (Bc * Lc)          // 32768 tokens

typedef __nv_bfloat16 bf16;

// ---------------- scratch (device globals; no allocs allowed) ----------------
__device__ float g_cnn[(size_t)Mtok * Hc];
__device__ float g_xn[(size_t)Mtok * Hc];
__device__ float g_U[(size_t)Mtok * 3 * Hc];
__device__ float g_blend[(size_t)Mtok * Hc];
__device__ float g_gated[(size_t)Mtok * Hc];
__device__ float g_t1[(size_t)Mtok * 2 * Hc];
// bf16 hi/lo activation copies
__device__ bf16 g_xh[(size_t)Mtok * Hc],      g_xl[(size_t)Mtok * Hc];
__device__ bf16 g_xnh[(size_t)Mtok * Hc],     g_xnl[(size_t)Mtok * Hc];
__device__ bf16 g_a1h[(size_t)Mtok * Hc],     g_a1l[(size_t)Mtok * Hc];
__device__ bf16 g_a2h[(size_t)Mtok * 2 * Hc], g_a2l[(size_t)Mtok * 2 * Hc];
// transposed bf16 split weights, layout [N][K]
__device__ bf16 g_WcT_hi[1024 * 4096], g_WcT_lo[1024 * 4096];
__device__ bf16 g_WuT_hi[3072 * 1024], g_WuT_lo[3072 * 1024];
__device__ bf16 g_W1T_hi[2048 * 1024], g_W1T_lo[2048 * 1024];
__device__ bf16 g_W2T_hi[1024 * 2048], g_W2T_lo[1024 * 2048];

// ---------------- helpers ----------------
__device__ __forceinline__ float blockReduceSum(float v) {
    __shared__ float red[32];
    int lane = threadIdx.x & 31;
    int wid  = threadIdx.x >> 5;
    #pragma unroll
    for (int o = 16; o > 0; o >>= 1) v += __shfl_xor_sync(0xffffffffu, v, o);
    if (lane == 0) red[wid] = v;
    __syncthreads();
    int nw = blockDim.x >> 5;
    if (wid == 0) {
        float s = (lane < nw) ? red[lane] : 0.0f;
        #pragma unroll
        for (int o = 16; o > 0; o >>= 1) s += __shfl_xor_sync(0xffffffffu, s, o);
        if (lane == 0) red[0] = s;
    }
    __syncthreads();
    float r = red[0];
    __syncthreads();
    return r;
}

__device__ __forceinline__ float geluf(float x) {
    return 0.5f * x * (1.0f + erff(x * 0.7071067811865476f));
}

__device__ __forceinline__ void split1(float v, bf16& h, bf16& l) {
    h = __float2bfloat16(v);
    l = __float2bfloat16(v - __bfloat162float(h));
}

__device__ __forceinline__ uint32_t cvta_s(const void* p) {
    uint32_t a;
    asm("{ .reg .u64 t; cvta.to.shared.u64 t, %1; cvt.u32.u64 %0, t; }" : "=r"(a) : "l"(p));
    return a;
}

// ---------------- weight prep ----------------
// fp32 [K][N] row-major -> bf16 hi/lo [N][K]
__global__ void wtrans_kernel(const float* __restrict__ in,
                              bf16* __restrict__ oh, bf16* __restrict__ ol,
                              int Kd, int N) {
    __shared__ float tile[32][33];
    int n0 = blockIdx.x * 32, k0 = blockIdx.y * 32;
    int tx = threadIdx.x, ty = threadIdx.y;  // 32 x 8
    #pragma unroll
    for (int i = 0; i < 32; i += 8)
        tile[ty + i][tx] = in[(size_t)(k0 + ty + i) * N + n0 + tx];
    __syncthreads();
    #pragma unroll
    for (int i = 0; i < 32; i += 8) {
        float v = tile[tx][ty + i];
        size_t o = (size_t)(n0 + ty + i) * Kd + k0 + tx;
        bf16 h, l; split1(v, h, l);
        oh[o] = h; ol[o] = l;
    }
}

// conv weights (ho,hi,k) -> [ho][k*1024+hi]
__global__ void wconv_kernel(const float* __restrict__ w,
                             bf16* __restrict__ oh, bf16* __restrict__ ol) {
    int ho = blockIdx.x;
    for (int hi = threadIdx.x; hi < 1024; hi += 256) {
        float4 v = *reinterpret_cast<const float4*>(w + ((size_t)ho * 1024 + hi) * 4);
        float vv[4] = {v.x, v.y, v.z, v.w};
        #pragma unroll
        for (int k = 0; k < 4; k++) {
            size_t o = (size_t)ho * 4096 + k * 1024 + hi;
            bf16 h, l; split1(vv[k], h, l);
            oh[o] = h; ol[o] = l;
        }
    }
}

// fp32 -> bf16 hi/lo elementwise
__global__ void fcvt_kernel(const float* __restrict__ in,
                            bf16* __restrict__ oh, bf16* __restrict__ ol) {
    size_t i = ((size_t)blockIdx.x * 256 + threadIdx.x) * 4;
    float4 v = *reinterpret_cast<const float4*>(in + i);
    bf16 h, l;
    split1(v.x, h, l); oh[i] = h;     ol[i] = l;
    split1(v.y, h, l); oh[i + 1] = h; ol[i + 1] = l;
    split1(v.z, h, l); oh[i + 2] = h; ol[i + 2] = l;
    split1(v.w, h, l); oh[i + 3] = h; ol[i + 3] = l;
}

// ---------------- HMMA bf16x3 GEMM (cp.async 3-stage + ldmatrix) ----------------
// C[M,N] = A @ B(+bias)(+resid); A: [M][K] bf16 hi/lo (CONV=1: implicit im2col of x),
// B: [N][K] bf16 hi/lo (the "col" operand of mma.row.col).
#define ROWB   80                 // padded SMEM row stride: 64B data + 16B pad
#define OPB    (128 * ROWB)       // one operand region per stage = 10240 B
#define STAGEB (4 * OPB)          // Ahi|Alo|Bhi|Blo = 40960 B
#define NST    3
#define SMEM_TOT (NST * STAGEB)   // 122880 B

#define MMA16816(d, a, b)                                                        \
    asm volatile("mma.sync.aligned.m16n8k16.row.col.f32.bf16.bf16.f32 "          \
                 "{%0,%1,%2,%3},{%4,%5,%6,%7},{%8,%9},{%0,%1,%2,%3};"            \
                 : "+f"((d)[0]), "+f"((d)[1]), "+f"((d)[2]), "+f"((d)[3])        \
                 : "r"((a)[0]), "r"((a)[1]), "r"((a)[2]), "r"((a)[3]),           \
                   "r"((b)[0]), "r"((b)[1]))

#define LDSM4(r0, r1, r2, r3, addr)                                              \
    asm volatile("ldmatrix.sync.aligned.m8n8.x4.shared.b16 {%0,%1,%2,%3}, [%4];" \
                 : "=r"(r0), "=r"(r1), "=r"(r2), "=r"(r3) : "r"(addr))

#define CPA(dst, src, sz)                                                        \
    asm volatile("cp.async.cg.shared.global [%0], [%1], 16, %2;"                 \
                 :: "r"(dst), "l"(src), "r"(sz) : "memory")

#define CPA_COMMIT() asm volatile("cp.async.commit_group;" ::: "memory")
#define CPA_WAIT1()  asm volatile("cp.async.wait_group 1;" ::: "memory")

template<int CONV>
__global__ void __launch_bounds__(256, 1)
mma_gemm(const bf16* __restrict__ Ahi, const bf16* __restrict__ Alo,
         const bf16* __restrict__ Bhi, const bf16* __restrict__ Blo,
         float* __restrict__ C,
         const float* __restrict__ bias, const float* __restrict__ resid,
         int N, int Kd)
{
    extern __shared__ char sm[];
    const uint32_t sb = cvta_s(sm);
    const int tid = threadIdx.x;
    const int wid = tid >> 5, lid = tid & 31;
    const int wm = wid >> 2, wn = wid & 3;         // 2 x 4 warp grid
    const int m0 = blockIdx.y * 128, n0 = blockIdx.x * 128;

    // cp.async: each thread covers rows {tid>>2, 64+(tid>>2)}, 16B chunk (tid&3)
    const int crow = tid >> 2, cc = tid & 3;

    // ldmatrix lane offsets
    const uint32_t aLane = (uint32_t)((lid & 15) * ROWB + (lid >> 4) * 16);
    const uint32_t bLane = (uint32_t)((((lid & 7) + ((lid >> 4) << 3)) * ROWB) +
                                      (((lid >> 3) & 1) * 16));

    float acc[4][4][4];
    #pragma unroll
    for (int i = 0; i < 4; i++)
        #pragma unroll
        for (int j = 0; j < 4; j++)
            #pragma unroll
            for (int q = 0; q < 4; q++) acc[i][j][q] = 0.0f;

    // ---- async tile load into stage slot ----
    #define ISSUE(slot, kg)                                                          \
        {                                                                            \
            uint32_t dbase = sb + (uint32_t)(slot) * STAGEB;                         \
            _Pragma("unroll")                                                        \
            for (int p = 0; p < 2; ++p) {                                            \
                int r = crow + p * 64;                                               \
                uint32_t off = (uint32_t)(r * ROWB + cc * 16);                       \
                size_t bo = (size_t)(n0 + r) * Kd + (kg) + cc * 8;                   \
                CPA(dbase + 2 * OPB + off, Bhi + bo, 16);                            \
                CPA(dbase + 3 * OPB + off, Blo + bo, 16);                            \
                if (CONV) {                                                          \
                    int kidx = (kg) >> 10;                                           \
                    bool ok = (((m0 + r) & (Lc - 1)) + kidx) >= 3;                   \
                    size_t ao = (size_t)(m0 + r + kidx - 3) * Hc +                   \
                                ((kg) & 1023) + cc * 8;                              \
                    const bf16* sh = ok ? Ahi + ao : Ahi;                            \
                    const bf16* sl = ok ? Alo + ao : Alo;                            \
                    int sz = ok ? 16 : 0;                                            \
                    CPA(dbase + 0 * OPB + off, sh, sz);                              \
                    CPA(dbase + 1 * OPB + off, sl, sz);                              \
                } else {                                                             \
                    size_t ao = (size_t)(m0 + r) * Kd + (kg) + cc * 8;               \
                    CPA(dbase + 0 * OPB + off, Ahi + ao, 16);                        \
                    CPA(dbase + 1 * OPB + off, Alo + ao, 16);                        \
                }                                                                    \
            }                                                                        \
        }

    const int T = Kd / 32;
    ISSUE(0, 0); CPA_COMMIT();
    ISSUE(1, 32); CPA_COMMIT();

    int slot = 0;
    for (int t = 0; t < T; ++t) {
        CPA_WAIT1();
        __syncthreads();
        if (t + 2 < T) {
            int ns = slot + 2; if (ns >= NST) ns -= NST;
            ISSUE(ns, (t + 2) * 32);
        }
        CPA_COMMIT();

        const uint32_t base = sb + (uint32_t)slot * STAGEB;
        #pragma unroll
        for (int ks = 0; ks < 2; ++ks) {
            const uint32_t ko = ks * 32;
            uint32_t ah[4][4], al[4][4], bh[4][2], bl[4][2];
            #pragma unroll
            for (int i = 0; i < 4; ++i) {
                uint32_t ra = base + (uint32_t)((wm * 64 + i * 16) * ROWB) + aLane + ko;
                LDSM4(ah[i][0], ah[i][1], ah[i][2], ah[i][3], ra);
                LDSM4(al[i][0], al[i][1], al[i][2], al[i][3], ra + OPB);
            }
            #pragma unroll
            for (int jp = 0; jp < 2; ++jp) {
                uint32_t rb = base + 2 * OPB +
                              (uint32_t)((wn * 32 + jp * 16) * ROWB) + bLane + ko;
                LDSM4(bh[2 * jp][0], bh[2 * jp][1], bh[2 * jp + 1][0], bh[2 * jp + 1][1], rb);
                LDSM4(bl[2 * jp][0], bl[2 * jp][1], bl[2 * jp + 1][0], bl[2 * jp + 1][1], rb + OPB);
            }
            #pragma unroll
            for (int i = 0; i < 4; ++i)
                #pragma unroll
                for (int j = 0; j < 4; ++j) {
                    MMA16816(acc[i][j], ah[i], bh[j]);
                    MMA16816(acc[i][j], ah[i], bl[j]);
                    MMA16816(acc[i][j], al[i], bh[j]);
                }
        }
        ++slot; if (slot >= NST) slot = 0;
    }

    // ---- epilogue ----
    const int g = lid >> 2, t4 = lid & 3;
    #pragma unroll
    for (int i = 0; i < 4; ++i) {
        int r0 = m0 + wm * 64 + i * 16 + g;
        #pragma unroll
        for (int j = 0; j < 4; ++j) {
            int ccl = n0 + wn * 32 + j * 8 + 2 * t4;
            float2 v0 = make_float2(acc[i][j][0], acc[i][j][1]);
            float2 v1 = make_float2(acc[i][j][2], acc[i][j][3]);
            if (bias) {
                float2 bb = *reinterpret_cast<const float2*>(bias + ccl);
                v0.x += bb.x; v0.y += bb.y; v1.x += bb.x; v1.y += bb.y;
            }
            if (resid) {
                float2 q0 = *reinterpret_cast<const float2*>(resid + (size_t)r0 * N + ccl);
                float2 q1 = *reinterpret_cast<const float2*>(resid + (size_t)(r0 + 8) * N + ccl);
                v0.x += q0.x; v0.y += q0.y; v1.x += q1.x; v1.y += q1.y;
            }
            *reinterpret_cast<float2*>(C + (size_t)r0 * N + ccl) = v0;
            *reinterpret_cast<float2*>(C + (size_t)(r0 + 8) * N + ccl) = v1;
        }
    }
    #undef ISSUE
}

// ---------------- layernorm over H=1024 (+ bf16 hi/lo emit) ----------------
__global__ void ln_kernel(const float* __restrict__ in, float* __restrict__ out,
                          bf16* __restrict__ oh, bf16* __restrict__ ol,
                          const float* __restrict__ w, const float* __restrict__ b) {
    int t = blockIdx.x, tid = threadIdx.x;
    const float* row = in + (size_t)t * Hc;
    float v[4];
    float s = 0.0f;
    #pragma unroll
    for (int i = 0; i < 4; i++) { v[i] = row[tid + i * 256]; s += v[i]; }
    s = blockReduceSum(s);
    float mean = s * (1.0f / Hc);
    float sq = 0.0f;
    #pragma unroll
    for (int i = 0; i < 4; i++) { float d = v[i] - mean; sq += d * d; }
    sq = blockReduceSum(sq);
    float rstd = rsqrtf(sq * (1.0f / Hc) + 1e-5f);
    #pragma unroll
    for (int i = 0; i < 4; i++) {
        int idx = tid + i * 256;
        float o = (v[i] - mean) * rstd * w[idx] + b[idx];
        out[(size_t)t * Hc + idx] = o;
        bf16 h, l; split1(o, h, l);
        oh[(size_t)t * Hc + idx] = h;
        ol[(size_t)t * Hc + idx] = l;
    }
}

// ---------------- SRU scan + lambda blend ----------------
__global__ void scan_kernel(const float* __restrict__ U, const float* __restrict__ xn,
                            const float* __restrict__ cnn, float* __restrict__ blend,
                            const float* __restrict__ vf_, const float* __restrict__ vr_,
                            const float* __restrict__ bf_, const float* __restrict__ br_,
                            const float* __restrict__ lam_, int Bv) {
    int g = blockIdx.x * blockDim.x + threadIdx.x;
    if (g >= Bv * Hc) return;
    int b = g >> 10, h = g & 1023;
    const float vf = vf_[h], vr = vr_[h], bfv = bf_[h], brv = br_[h], lam = lam_[h];
    const float SCALE_X = sqrtf(1.0f + expf(-4.0f));
    size_t iu = ((size_t)b * Lc) * (3 * Hc) + h;
    size_t ix = ((size_t)b * Lc) * Hc + h;
    float c = 0.0f;
    #pragma unroll 2
    for (int l = 0; l < Lc; ++l) {
        float u0 = U[iu], u1 = U[iu + Hc], u2 = U[iu + 2 * Hc];
        float xr = xn[ix] * SCALE_X;
        float cnv = cnn[ix];
        float f = 1.0f / (1.0f + __expf(-(fmaf(c, vf, u1) + bfv)));
        float cn = fmaf(f, c - u0, u0);
        float r = 1.0f / (1.0f + __expf(-(fmaf(c, vr, u2) + brv)));
        float th = tanhf(cn);
        float ht = fmaf(r, th - xr, xr);
        blend[ix] = fmaf(lam, cnv - ht, ht);
        c = cn;
        iu += 3 * Hc;
        ix += Hc;
    }
}

// ---------------- rmsnorm + gate + ln1 + gelu -> gated(f32), a1 hi/lo ----------------
__global__ void rms_gate_ln1_kernel(const float* __restrict__ blend, const float* __restrict__ x,
                                    const float* __restrict__ rmsw,
                                    const float* __restrict__ ln1w, const float* __restrict__ ln1b,
                                    float* __restrict__ gated,
                                    bf16* __restrict__ a1h, bf16* __restrict__ a1l) {
    int t = blockIdx.x, tid = threadIdx.x;
    size_t base = (size_t)t * Hc;
    float v[4], g[4];
    float sq = 0.0f;
    #pragma unroll
    for (int i = 0; i < 4; i++) { v[i] = blend[base + tid + i * 256]; sq += v[i] * v[i]; }
    sq = blockReduceSum(sq);
    float rs = rsqrtf(sq * (1.0f / Hc) + 1e-6f);
    float s = 0.0f;
    #pragma unroll
    for (int i = 0; i < 4; i++) {
        int idx = tid + i * 256;
        float o = rmsw[idx] * v[i] * rs;
        g[i] = o * x[base + idx];
        gated[base + idx] = g[i];
        s += g[i];
    }
    s = blockReduceSum(s);
    float mean = s * (1.0f / Hc);
    float var = 0.0f;
    #pragma unroll
    for (int i = 0; i < 4; i++) { float d = g[i] - mean; var += d * d; }
    var = blockReduceSum(var);
    float rstd = rsqrtf(var * (1.0f / Hc) + 1e-5f);
    #pragma unroll
    for (int i = 0; i < 4; i++) {
        int idx = tid + i * 256;
        float a = geluf((g[i] - mean) * rstd * ln1w[idx] + ln1b[idx]);
        bf16 h, l; split1(a, h, l);
        a1h[base + idx] = h;
        a1l[base + idx] = l;
    }
}

// ---------------- ln2 + gelu over 2H -> a2 hi/lo ----------------
__global__ void ln2_gelu_kernel(const float* __restrict__ t1,
                                bf16* __restrict__ a2h, bf16* __restrict__ a2l,
                                const float* __restrict__ w, const float* __restrict__ b) {
    int t = blockIdx.x, tid = threadIdx.x;
    const int NN = 2 * Hc;
    size_t base = (size_t)t * NN;
    float v[8];
    float s = 0.0f;
    #pragma unroll
    for (int i = 0; i < 8; i++) { v[i] = t1[base + tid + i * 256]; s += v[i]; }
    s = blockReduceSum(s);
    float mean = s * (1.0f / NN);
    float sq = 0.0f;
    #pragma unroll
    for (int i = 0; i < 8; i++) { float d = v[i] - mean; sq += d * d; }
    sq = blockReduceSum(sq);
    float rstd = rsqrtf(sq * (1.0f / NN) + 1e-5f);
    #pragma unroll
    for (int i = 0; i < 8; i++) {
        int idx = tid + i * 256;
        float a = geluf((v[i] - mean) * rstd * w[idx] + b[idx]);
        bf16 h, l; split1(a, h, l);
        a2h[base + idx] = h;
        a2l[base + idx] = l;
    }
}

// ---------------- launch ----------------
extern "C" void kernel_launch(void* const* d_in, const int* in_sizes, int n_in,
                              void* d_out, int out_size) {
    const float* x        = (const float*)d_in[0];
    const float* conv_w   = (const float*)d_in[1];
    const float* conv_b   = (const float*)d_in[2];
    const float* sru_ln_w = (const float*)d_in[3];
    const float* sru_ln_b = (const float*)d_in[4];
    const float* sru_W    = (const float*)d_in[5];
    const float* sru_vf   = (const float*)d_in[6];
    const float* sru_vr   = (const float*)d_in[7];
    const float* sru_bf   = (const float*)d_in[8];
    const float* sru_br   = (const float*)d_in[9];
    const float* lambda_w = (const float*)d_in[10];
    const float* rms_w    = (const float*)d_in[11];
    const float* ln1_w    = (const float*)d_in[12];
    const float* ln1_b    = (const float*)d_in[13];
    const float* lin1_w   = (const float*)d_in[14];
    const float* ln2_w    = (const float*)d_in[15];
    const float* ln2_b    = (const float*)d_in[16];
    const float* lin2_w   = (const float*)d_in[17];
    const float* lin2_b   = (const float*)d_in[18];

    int Bv = in_sizes[0] / (Lc * Hc);
    int M  = Bv * Lc;

    float *cnn, *xn, *U, *blend, *gated, *t1;
    bf16 *xh, *xl, *xnh, *xnl, *a1h, *a1l, *a2h, *a2l;
    bf16 *WcH, *WcL, *WuH, *WuL, *W1H, *W1L, *W2H, *W2L;
    cudaGetSymbolAddress((void**)&cnn,   g_cnn);
    cudaGetSymbolAddress((void**)&xn,    g_xn);
    cudaGetSymbolAddress((void**)&U,     g_U);
    cudaGetSymbolAddress((void**)&blend, g_blend);
    cudaGetSymbolAddress((void**)&gated, g_gated);
    cudaGetSymbolAddress((void**)&t1,    g_t1);
    cudaGetSymbolAddress((void**)&xh,  g_xh);  cudaGetSymbolAddress((void**)&xl,  g_xl);
    cudaGetSymbolAddress((void**)&xnh, g_xnh); cudaGetSymbolAddress((void**)&xnl, g_xnl);
    cudaGetSymbolAddress((void**)&a1h, g_a1h); cudaGetSymbolAddress((void**)&a1l, g_a1l);
    cudaGetSymbolAddress((void**)&a2h, g_a2h); cudaGetSymbolAddress((void**)&a2l, g_a2l);
    cudaGetSymbolAddress((void**)&WcH, g_WcT_hi); cudaGetSymbolAddress((void**)&WcL, g_WcT_lo);
    cudaGetSymbolAddress((void**)&WuH, g_WuT_hi); cudaGetSymbolAddress((void**)&WuL, g_WuT_lo);
    cudaGetSymbolAddress((void**)&W1H, g_W1T_hi); cudaGetSymbolAddress((void**)&W1L, g_W1T_lo);
    cudaGetSymbolAddress((void**)&W2H, g_W2T_hi); cudaGetSymbolAddress((void**)&W2L, g_W2T_lo);

    cudaFuncSetAttribute(mma_gemm<0>, cudaFuncAttributeMaxDynamicSharedMemorySize, SMEM_TOT);
    cudaFuncSetAttribute(mma_gemm<1>, cudaFuncAttributeMaxDynamicSharedMemorySize, SMEM_TOT);

    // weight + input prep
    wconv_kernel<<<1024, 256>>>(conv_w, WcH, WcL);
    wtrans_kernel<<<dim3(3072 / 32, 1024 / 32), dim3(32, 8)>>>(sru_W, WuH, WuL, 1024, 3072);
    wtrans_kernel<<<dim3(2048 / 32, 1024 / 32), dim3(32, 8)>>>(lin1_w, W1H, W1L, 1024, 2048);
    wtrans_kernel<<<dim3(1024 / 32, 2048 / 32), dim3(32, 8)>>>(lin2_w, W2H, W2L, 2048, 1024);
    fcvt_kernel<<<(size_t)M * Hc / 1024, 256>>>(x, xh, xl);

    // 1. causal conv as GEMM
    mma_gemm<1><<<dim3(Hc / 128, M / 128), 256, SMEM_TOT>>>(xh, xl, WcH, WcL, cnn, conv_b, nullptr, Hc, 4 * Hc);
    // 2. layernorm (+ bf16 split)
    ln_kernel<<<M, 256>>>(cnn, xn, xnh, xnl, sru_ln_w, sru_ln_b);
    // 3. U = xn @ sru_W
    mma_gemm<0><<<dim3(3 * Hc / 128, M / 128), 256, SMEM_TOT>>>(xnh, xnl, WuH, WuL, U, nullptr, nullptr, 3 * Hc, Hc);
    // 4. SRU scan + blend
    scan_kernel<<<(Bv * Hc + 127) / 128, 128>>>(U, xn, cnn, blend,
                                                sru_vf, sru_vr, sru_bf, sru_br, lambda_w, Bv);
    // 5. rmsnorm + gate + ln1 + gelu
    rms_gate_ln1_kernel<<<M, 256>>>(blend, x, rms_w, ln1_w, ln1_b, gated, a1h, a1l);
    // 6. t1 = a1 @ lin1_w
    mma_gemm<0><<<dim3(2 * Hc / 128, M / 128), 256, SMEM_TOT>>>(a1h, a1l, W1H, W1L, t1, nullptr, nullptr, 2 * Hc, Hc);
    // 7. a2 = gelu(ln2(t1))
    ln2_gelu_kernel<<<M, 256>>>(t1, a2h, a2l, ln2_w, ln2_b);
    // 8. out = a2 @ lin2_w + lin2_b + gated
    mma_gemm<0><<<dim3(Hc / 128, M / 128), 256, SMEM_TOT>>>(a2h, a2l, W2H, W2L, (float*)d_out, lin2_b, gated, Hc, 2 * Hc);
}

// round 5
// speedup vs baseline: 3.6996x; 1.8608x over previous
#include <cuda_runtime.h>
#include <cuda_fp16.h>
#include <math.h>
#include <stdint.h>

// ---------------- problem constants ----------------
#define Hc   1024
#define Lc   4096
#define Bc   8
#define Mtok (Bc * Lc)          // 32768 tokens

typedef __half fp16;

// ---------------- scratch (device globals; no allocs allowed) ----------------
__device__ float g_cnn[(size_t)Mtok * Hc];
__device__ float g_xn[(size_t)Mtok * Hc];
__device__ float g_U[(size_t)Mtok * 3 * Hc];
__device__ float g_blend[(size_t)Mtok * Hc];
__device__ float g_gated[(size_t)Mtok * Hc];
__device__ float g_t1[(size_t)Mtok * 2 * Hc];
// fp16 activation copies
__device__ fp16 g_xh[(size_t)Mtok * Hc];
__device__ fp16 g_xnh[(size_t)Mtok * Hc];
__device__ fp16 g_a1h[(size_t)Mtok * Hc];
__device__ fp16 g_a2h[(size_t)Mtok * 2 * Hc];
// transposed fp16 weights, layout [N][K]
__device__ fp16 g_WcT[1024 * 4096];
__device__ fp16 g_WuT[3072 * 1024];
__device__ fp16 g_W1T[2048 * 1024];
__device__ fp16 g_W2T[1024 * 2048];

// ---------------- helpers ----------------
__device__ __forceinline__ float blockReduceSum(float v) {
    __shared__ float red[32];
    int lane = threadIdx.x & 31;
    int wid  = threadIdx.x >> 5;
    #pragma unroll
    for (int o = 16; o > 0; o >>= 1) v += __shfl_xor_sync(0xffffffffu, v, o);
    if (lane == 0) red[wid] = v;
    __syncthreads();
    int nw = blockDim.x >> 5;
    if (wid == 0) {
        float s = (lane < nw) ? red[lane] : 0.0f;
        #pragma unroll
        for (int o = 16; o > 0; o >>= 1) s += __shfl_xor_sync(0xffffffffu, s, o);
        if (lane == 0) red[0] = s;
    }
    __syncthreads();
    float r = red[0];
    __syncthreads();
    return r;
}

__device__ __forceinline__ float geluf(float x) {
    return 0.5f * x * (1.0f + erff(x * 0.7071067811865476f));
}

__device__ __forceinline__ uint32_t cvta_s(const void* p) {
    uint32_t a;
    asm("{ .reg .u64 t; cvta.to.shared.u64 t, %1; cvt.u32.u64 %0, t; }" : "=r"(a) : "l"(p));
    return a;
}

// ---------------- weight prep ----------------
// fp32 [K][N] row-major -> fp16 [N][K]
__global__ void wtrans_kernel(const float* __restrict__ in,
                              fp16* __restrict__ oh, int Kd, int N) {
    __shared__ float tile[32][33];
    int n0 = blockIdx.x * 32, k0 = blockIdx.y * 32;
    int tx = threadIdx.x, ty = threadIdx.y;  // 32 x 8
    #pragma unroll
    for (int i = 0; i < 32; i += 8)
        tile[ty + i][tx] = in[(size_t)(k0 + ty + i) * N + n0 + tx];
    __syncthreads();
    #pragma unroll
    for (int i = 0; i < 32; i += 8) {
        float v = tile[tx][ty + i];
        oh[(size_t)(n0 + ty + i) * Kd + k0 + tx] = __float2half(v);
    }
}

// conv weights (ho,hi,k) -> [ho][k*1024+hi]
__global__ void wconv_kernel(const float* __restrict__ w, fp16* __restrict__ oh) {
    int ho = blockIdx.x;
    for (int hi = threadIdx.x; hi < 1024; hi += 256) {
        float4 v = *reinterpret_cast<const float4*>(w + ((size_t)ho * 1024 + hi) * 4);
        float vv[4] = {v.x, v.y, v.z, v.w};
        #pragma unroll
        for (int k = 0; k < 4; k++)
            oh[(size_t)ho * 4096 + k * 1024 + hi] = __float2half(vv[k]);
    }
}

// fp32 -> fp16 elementwise
__global__ void fcvt_kernel(const float* __restrict__ in, fp16* __restrict__ oh) {
    size_t i = ((size_t)blockIdx.x * 256 + threadIdx.x) * 4;
    float4 v = *reinterpret_cast<const float4*>(in + i);
    __half2 a = __floats2half2_rn(v.x, v.y);
    __half2 b = __floats2half2_rn(v.z, v.w);
    *reinterpret_cast<__half2*>(oh + i)     = a;
    *reinterpret_cast<__half2*>(oh + i + 2) = b;
}

// ---------------- fp16 HMMA GEMM (cp.async 3-stage + ldmatrix) ----------------
// C[M,N] = A @ B(+bias)(+resid); A: [M][K] fp16 (CONV=1: implicit im2col of x),
// B: [N][K] fp16 (the "col" operand of mma.row.col).
#define ROWB   80                 // padded SMEM row stride: 64B data + 16B pad
#define OPB    (128 * ROWB)       // one operand region per stage = 10240 B
#define STAGEB (2 * OPB)          // A|B = 20480 B
#define NST    3
#define SMEM_TOT (NST * STAGEB)   // 61440 B

#define MMA16816(d, a, b)                                                        \
    asm volatile("mma.sync.aligned.m16n8k16.row.col.f32.f16.f16.f32 "            \
                 "{%0,%1,%2,%3},{%4,%5,%6,%7},{%8,%9},{%0,%1,%2,%3};"            \
                 : "+f"((d)[0]), "+f"((d)[1]), "+f"((d)[2]), "+f"((d)[3])        \
                 : "r"((a)[0]), "r"((a)[1]), "r"((a)[2]), "r"((a)[3]),           \
                   "r"((b)[0]), "r"((b)[1]))

#define LDSM4(r0, r1, r2, r3, addr)                                              \
    asm volatile("ldmatrix.sync.aligned.m8n8.x4.shared.b16 {%0,%1,%2,%3}, [%4];" \
                 : "=r"(r0), "=r"(r1), "=r"(r2), "=r"(r3) : "r"(addr))

#define CPA(dst, src, sz)                                                        \
    asm volatile("cp.async.cg.shared.global [%0], [%1], 16, %2;"                 \
                 :: "r"(dst), "l"(src), "r"(sz) : "memory")

#define CPA_COMMIT() asm volatile("cp.async.commit_group;" ::: "memory")
#define CPA_WAIT1()  asm volatile("cp.async.wait_group 1;" ::: "memory")

template<int CONV>
__global__ void __launch_bounds__(256, 2)
mma_gemm(const fp16* __restrict__ Ah, const fp16* __restrict__ Bh,
         float* __restrict__ C,
         const float* __restrict__ bias, const float* __restrict__ resid,
         int N, int Kd)
{
    extern __shared__ char sm[];
    const uint32_t sb = cvta_s(sm);
    const int tid = threadIdx.x;
    const int wid = tid >> 5, lid = tid & 31;
    const int wm = wid >> 2, wn = wid & 3;         // 2 x 4 warp grid
    const int m0 = blockIdx.y * 128, n0 = blockIdx.x * 128;

    // cp.async: each thread covers rows {tid>>2, 64+(tid>>2)}, 16B chunk (tid&3)
    const int crow = tid >> 2, cc = tid & 3;

    // ldmatrix lane offsets
    const uint32_t aLane = (uint32_t)((lid & 15) * ROWB + (lid >> 4) * 16);
    const uint32_t bLane = (uint32_t)((((lid & 7) + ((lid >> 4) << 3)) * ROWB) +
                                      (((lid >> 3) & 1) * 16));

    float acc[4][4][4];
    #pragma unroll
    for (int i = 0; i < 4; i++)
        #pragma unroll
        for (int j = 0; j < 4; j++)
            #pragma unroll
            for (int q = 0; q < 4; q++) acc[i][j][q] = 0.0f;

    // ---- async tile load into stage slot ----
    #define ISSUE(slot, kg)                                                          \
        {                                                                            \
            uint32_t dbase = sb + (uint32_t)(slot) * STAGEB;                         \
            _Pragma("unroll")                                                        \
            for (int p = 0; p < 2; ++p) {                                            \
                int r = crow + p * 64;                                               \
                uint32_t off = (uint32_t)(r * ROWB + cc * 16);                       \
                size_t bo = (size_t)(n0 + r) * Kd + (kg) + cc * 8;                   \
                CPA(dbase + OPB + off, Bh + bo, 16);                                 \
                if (CONV) {                                                          \
                    int kidx = (kg) >> 10;                                           \
                    bool ok = (((m0 + r) & (Lc - 1)) + kidx) >= 3;                   \
                    size_t ao = (size_t)(m0 + r + kidx - 3) * Hc +                   \
                                ((kg) & 1023) + cc * 8;                              \
                    const fp16* sh = ok ? Ah + ao : Ah;                              \
                    int sz = ok ? 16 : 0;                                            \
                    CPA(dbase + off, sh, sz);                                        \
                } else {                                                             \
                    size_t ao = (size_t)(m0 + r) * Kd + (kg) + cc * 8;               \
                    CPA(dbase + off, Ah + ao, 16);                                   \
                }                                                                    \
            }                                                                        \
        }

    const int T = Kd / 32;
    ISSUE(0, 0); CPA_COMMIT();
    ISSUE(1, 32); CPA_COMMIT();

    int slot = 0;
    for (int t = 0; t < T; ++t) {
        CPA_WAIT1();
        __syncthreads();
        if (t + 2 < T) {
            int ns = slot + 2; if (ns >= NST) ns -= NST;
            ISSUE(ns, (t + 2) * 32);
        }
        CPA_COMMIT();

        const uint32_t base = sb + (uint32_t)slot * STAGEB;
        #pragma unroll
        for (int ks = 0; ks < 2; ++ks) {
            const uint32_t ko = ks * 32;
            uint32_t ah[4][4], bh[4][2];
            #pragma unroll
            for (int i = 0; i < 4; ++i) {
                uint32_t ra = base + (uint32_t)((wm * 64 + i * 16) * ROWB) + aLane + ko;
                LDSM4(ah[i][0], ah[i][1], ah[i][2], ah[i][3], ra);
            }
            #pragma unroll
            for (int jp = 0; jp < 2; ++jp) {
                uint32_t rb = base + OPB +
                              (uint32_t)((wn * 32 + jp * 16) * ROWB) + bLane + ko;
                LDSM4(bh[2 * jp][0], bh[2 * jp][1], bh[2 * jp + 1][0], bh[2 * jp + 1][1], rb);
            }
            #pragma unroll
            for (int i = 0; i < 4; ++i)
                #pragma unroll
                for (int j = 0; j < 4; ++j)
                    MMA16816(acc[i][j], ah[i], bh[j]);
        }
        ++slot; if (slot >= NST) slot = 0;
    }

    // ---- epilogue ----
    const int g = lid >> 2, t4 = lid & 3;
    #pragma unroll
    for (int i = 0; i < 4; ++i) {
        int r0 = m0 + wm * 64 + i * 16 + g;
        #pragma unroll
        for (int j = 0; j < 4; ++j) {
            int ccl = n0 + wn * 32 + j * 8 + 2 * t4;
            float2 v0 = make_float2(acc[i][j][0], acc[i][j][1]);
            float2 v1 = make_float2(acc[i][j][2], acc[i][j][3]);
            if (bias) {
                float2 bb = *reinterpret_cast<const float2*>(bias + ccl);
                v0.x += bb.x; v0.y += bb.y; v1.x += bb.x; v1.y += bb.y;
            }
            if (resid) {
                float2 q0 = *reinterpret_cast<const float2*>(resid + (size_t)r0 * N + ccl);
                float2 q1 = *reinterpret_cast<const float2*>(resid + (size_t)(r0 + 8) * N + ccl);
                v0.x += q0.x; v0.y += q0.y; v1.x += q1.x; v1.y += q1.y;
            }
            *reinterpret_cast<float2*>(C + (size_t)r0 * N + ccl) = v0;
            *reinterpret_cast<float2*>(C + (size_t)(r0 + 8) * N + ccl) = v1;
        }
    }
    #undef ISSUE
}

// ---------------- layernorm over H=1024 (+ fp16 emit) ----------------
__global__ void ln_kernel(const float* __restrict__ in, float* __restrict__ out,
                          fp16* __restrict__ oh,
                          const float* __restrict__ w, const float* __restrict__ b) {
    int t = blockIdx.x, tid = threadIdx.x;
    const float* row = in + (size_t)t * Hc;
    float v[4];
    float s = 0.0f;
    #pragma unroll
    for (int i = 0; i < 4; i++) { v[i] = row[tid + i * 256]; s += v[i]; }
    s = blockReduceSum(s);
    float mean = s * (1.0f / Hc);
    float sq = 0.0f;
    #pragma unroll
    for (int i = 0; i < 4; i++) { float d = v[i] - mean; sq += d * d; }
    sq = blockReduceSum(sq);
    float rstd = rsqrtf(sq * (1.0f / Hc) + 1e-5f);
    #pragma unroll
    for (int i = 0; i < 4; i++) {
        int idx = tid + i * 256;
        float o = (v[i] - mean) * rstd * w[idx] + b[idx];
        out[(size_t)t * Hc + idx] = o;
        oh[(size_t)t * Hc + idx] = __float2half(o);
    }
}

// ---------------- SRU scan + lambda blend ----------------
__global__ void scan_kernel(const float* __restrict__ U, const float* __restrict__ xn,
                            const float* __restrict__ cnn, float* __restrict__ blend,
                            const float* __restrict__ vf_, const float* __restrict__ vr_,
                            const float* __restrict__ bf_, const float* __restrict__ br_,
                            const float* __restrict__ lam_, int Bv) {
    int g = blockIdx.x * blockDim.x + threadIdx.x;
    if (g >= Bv * Hc) return;
    int b = g >> 10, h = g & 1023;
    const float vf = vf_[h], vr = vr_[h], bfv = bf_[h], brv = br_[h], lam = lam_[h];
    const float SCALE_X = sqrtf(1.0f + expf(-4.0f));
    size_t iu = ((size_t)b * Lc) * (3 * Hc) + h;
    size_t ix = ((size_t)b * Lc) * Hc + h;
    float c = 0.0f;
    #pragma unroll 2
    for (int l = 0; l < Lc; ++l) {
        float u0 = U[iu], u1 = U[iu + Hc], u2 = U[iu + 2 * Hc];
        float xr = xn[ix] * SCALE_X;
        float cnv = cnn[ix];
        float f = 1.0f / (1.0f + __expf(-(fmaf(c, vf, u1) + bfv)));
        float cn = fmaf(f, c - u0, u0);
        float r = 1.0f / (1.0f + __expf(-(fmaf(c, vr, u2) + brv)));
        float th = tanhf(cn);
        float ht = fmaf(r, th - xr, xr);
        blend[ix] = fmaf(lam, cnv - ht, ht);
        c = cn;
        iu += 3 * Hc;
        ix += Hc;
    }
}

// ---------------- rmsnorm + gate + ln1 + gelu -> gated(f32), a1 fp16 ----------------
__global__ void rms_gate_ln1_kernel(const float* __restrict__ blend, const float* __restrict__ x,
                                    const float* __restrict__ rmsw,
                                    const float* __restrict__ ln1w, const float* __restrict__ ln1b,
                                    float* __restrict__ gated, fp16* __restrict__ a1h) {
    int t = blockIdx.x, tid = threadIdx.x;
    size_t base = (size_t)t * Hc;
    float v[4], g[4];
    float sq = 0.0f;
    #pragma unroll
    for (int i = 0; i < 4; i++) { v[i] = blend[base + tid + i * 256]; sq += v[i] * v[i]; }
    sq = blockReduceSum(sq);
    float rs = rsqrtf(sq * (1.0f / Hc) + 1e-6f);
    float s = 0.0f;
    #pragma unroll
    for (int i = 0; i < 4; i++) {
        int idx = tid + i * 256;
        float o = rmsw[idx] * v[i] * rs;
        g[i] = o * x[base + idx];
        gated[base + idx] = g[i];
        s += g[i];
    }
    s = blockReduceSum(s);
    float mean = s * (1.0f / Hc);
    float var = 0.0f;
    #pragma unroll
    for (int i = 0; i < 4; i++) { float d = g[i] - mean; var += d * d; }
    var = blockReduceSum(var);
    float rstd = rsqrtf(var * (1.0f / Hc) + 1e-5f);
    #pragma unroll
    for (int i = 0; i < 4; i++) {
        int idx = tid + i * 256;
        float a = geluf((g[i] - mean) * rstd * ln1w[idx] + ln1b[idx]);
        a1h[base + idx] = __float2half(a);
    }
}

// ---------------- ln2 + gelu over 2H -> a2 fp16 ----------------
__global__ void ln2_gelu_kernel(const float* __restrict__ t1, fp16* __restrict__ a2h,
                                const float* __restrict__ w, const float* __restrict__ b) {
    int t = blockIdx.x, tid = threadIdx.x;
    const int NN = 2 * Hc;
    size_t base = (size_t)t * NN;
    float v[8];
    float s = 0.0f;
    #pragma unroll
    for (int i = 0; i < 8; i++) { v[i] = t1[base + tid + i * 256]; s += v[i]; }
    s = blockReduceSum(s);
    float mean = s * (1.0f / NN);
    float sq = 0.0f;
    #pragma unroll
    for (int i = 0; i < 8; i++) { float d = v[i] - mean; sq += d * d; }
    sq = blockReduceSum(sq);
    float rstd = rsqrtf(sq * (1.0f / NN) + 1e-5f);
    #pragma unroll
    for (int i = 0; i < 8; i++) {
        int idx = tid + i * 256;
        float a = geluf((v[i] - mean) * rstd * w[idx] + b[idx]);
        a2h[base + idx] = __float2half(a);
    }
}

// ---------------- launch ----------------
extern "C" void kernel_launch(void* const* d_in, const int* in_sizes, int n_in,
                              void* d_out, int out_size) {
    const float* x        = (const float*)d_in[0];
    const float* conv_w   = (const float*)d_in[1];
    const float* conv_b   = (const float*)d_in[2];
    const float* sru_ln_w = (const float*)d_in[3];
    const float* sru_ln_b = (const float*)d_in[4];
    const float* sru_W    = (const float*)d_in[5];
    const float* sru_vf   = (const float*)d_in[6];
    const float* sru_vr   = (const float*)d_in[7];
    const float* sru_bf   = (const float*)d_in[8];
    const float* sru_br   = (const float*)d_in[9];
    const float* lambda_w = (const float*)d_in[10];
    const float* rms_w    = (const float*)d_in[11];
    const float* ln1_w    = (const float*)d_in[12];
    const float* ln1_b    = (const float*)d_in[13];
    const float* lin1_w   = (const float*)d_in[14];
    const float* ln2_w    = (const float*)d_in[15];
    const float* ln2_b    = (const float*)d_in[16];
    const float* lin2_w   = (const float*)d_in[17];
    const float* lin2_b   = (const float*)d_in[18];

    int Bv = in_sizes[0] / (Lc * Hc);
    int M  = Bv * Lc;

    float *cnn, *xn, *U, *blend, *gated, *t1;
    fp16 *xh, *xnh, *a1h, *a2h, *Wc, *Wu, *W1, *W2;
    cudaGetSymbolAddress((void**)&cnn,   g_cnn);
    cudaGetSymbolAddress((void**)&xn,    g_xn);
    cudaGetSymbolAddress((void**)&U,     g_U);
    cudaGetSymbolAddress((void**)&blend, g_blend);
    cudaGetSymbolAddress((void**)&gated, g_gated);
    cudaGetSymbolAddress((void**)&t1,    g_t1);
    cudaGetSymbolAddress((void**)&xh,  g_xh);
    cudaGetSymbolAddress((void**)&xnh, g_xnh);
    cudaGetSymbolAddress((void**)&a1h, g_a1h);
    cudaGetSymbolAddress((void**)&a2h, g_a2h);
    cudaGetSymbolAddress((void**)&Wc, g_WcT);
    cudaGetSymbolAddress((void**)&Wu, g_WuT);
    cudaGetSymbolAddress((void**)&W1, g_W1T);
    cudaGetSymbolAddress((void**)&W2, g_W2T);

    cudaFuncSetAttribute(mma_gemm<0>, cudaFuncAttributeMaxDynamicSharedMemorySize, SMEM_TOT);
    cudaFuncSetAttribute(mma_gemm<1>, cudaFuncAttributeMaxDynamicSharedMemorySize, SMEM_TOT);

    // weight + input prep
    wconv_kernel<<<1024, 256>>>(conv_w, Wc);
    wtrans_kernel<<<dim3(3072 / 32, 1024 / 32), dim3(32, 8)>>>(sru_W, Wu, 1024, 3072);
    wtrans_kernel<<<dim3(2048 / 32, 1024 / 32), dim3(32, 8)>>>(lin1_w, W1, 1024, 2048);
    wtrans_kernel<<<dim3(1024 / 32, 2048 / 32), dim3(32, 8)>>>(lin2_w, W2, 2048, 1024);
    fcvt_kernel<<<(size_t)M * Hc / 1024, 256>>>(x, xh);

    // 1. causal conv as GEMM
    mma_gemm<1><<<dim3(Hc / 128, M / 128), 256, SMEM_TOT>>>(xh, Wc, cnn, conv_b, nullptr, Hc, 4 * Hc);
    // 2. layernorm (+ fp16 copy)
    ln_kernel<<<M, 256>>>(cnn, xn, xnh, sru_ln_w, sru_ln_b);
    // 3. U = xn @ sru_W
    mma_gemm<0><<<dim3(3 * Hc / 128, M / 128), 256, SMEM_TOT>>>(xnh, Wu, U, nullptr, nullptr, 3 * Hc, Hc);
    // 4. SRU scan + blend
    scan_kernel<<<(Bv * Hc + 127) / 128, 128>>>(U, xn, cnn, blend,
                                                sru_vf, sru_vr, sru_bf, sru_br, lambda_w, Bv);
    // 5. rmsnorm + gate + ln1 + gelu
    rms_gate_ln1_kernel<<<M, 256>>>(blend, x, rms_w, ln1_w, ln1_b, gated, a1h);
    // 6. t1 = a1 @ lin1_w
    mma_gemm<0><<<dim3(2 * Hc / 128, M / 128), 256, SMEM_TOT>>>(a1h, W1, t1, nullptr, nullptr, 2 * Hc, Hc);
    // 7. a2 = gelu(ln2(t1))
    ln2_gelu_kernel<<<M, 256>>>(t1, a2h, ln2_w, ln2_b);
    // 8. out = a2 @ lin2_w + lin2_b + gated
    mma_gemm<0><<<dim3(Hc / 128, M / 128), 256, SMEM_TOT>>>(a2h, W2, (float*)d_out, lin2_b, gated, Hc, 2 * Hc);
}

// round 6
// speedup vs baseline: 5.5081x; 1.4888x over previous
#include <cuda_runtime.h>
#include <cuda_fp16.h>
#include <math.h>
#include <stdint.h>

// ---------------- problem constants ----------------
#define Hc   1024
#define Lc   4096
#define Bc   8
#define Mtok (Bc * Lc)          // 32768 tokens

typedef __half fp16;

// ---------------- scratch (device globals; no allocs allowed) ----------------
__device__ float g_cnn[(size_t)Mtok * Hc];
__device__ float g_xn[(size_t)Mtok * Hc];
__device__ float g_U[(size_t)Mtok * 3 * Hc];
__device__ float g_blend[(size_t)Mtok * Hc];
__device__ float g_gated[(size_t)Mtok * Hc];
__device__ float g_t1[(size_t)Mtok * 2 * Hc];
// fp16 activation copies
__device__ fp16 g_xh[(size_t)Mtok * Hc];
__device__ fp16 g_xnh[(size_t)Mtok * Hc];
__device__ fp16 g_a1h[(size_t)Mtok * Hc];
__device__ fp16 g_a2h[(size_t)Mtok * 2 * Hc];
// transposed fp16 weights, layout [N][K]
__device__ fp16 g_WcT[1024 * 4096];
__device__ fp16 g_WuT[3072 * 1024];
__device__ fp16 g_W1T[2048 * 1024];
__device__ fp16 g_W2T[1024 * 2048];

// ---------------- helpers ----------------
__device__ __forceinline__ float blockReduceSum(float v) {
    __shared__ float red[32];
    int lane = threadIdx.x & 31;
    int wid  = threadIdx.x >> 5;
    #pragma unroll
    for (int o = 16; o > 0; o >>= 1) v += __shfl_xor_sync(0xffffffffu, v, o);
    if (lane == 0) red[wid] = v;
    __syncthreads();
    int nw = blockDim.x >> 5;
    if (wid == 0) {
        float s = (lane < nw) ? red[lane] : 0.0f;
        #pragma unroll
        for (int o = 16; o > 0; o >>= 1) s += __shfl_xor_sync(0xffffffffu, s, o);
        if (lane == 0) red[0] = s;
    }
    __syncthreads();
    float r = red[0];
    __syncthreads();
    return r;
}

__device__ __forceinline__ float geluf(float x) {
    return 0.5f * x * (1.0f + erff(x * 0.7071067811865476f));
}

__device__ __forceinline__ uint32_t cvta_s(const void* p) {
    uint32_t a;
    asm("{ .reg .u64 t; cvta.to.shared.u64 t, %1; cvt.u32.u64 %0, t; }" : "=r"(a) : "l"(p));
    return a;
}

// ---------------- weight prep ----------------
// fp32 [K][N] row-major -> fp16 [N][K]
__global__ void wtrans_kernel(const float* __restrict__ in,
                              fp16* __restrict__ oh, int Kd, int N) {
    __shared__ float tile[32][33];
    int n0 = blockIdx.x * 32, k0 = blockIdx.y * 32;
    int tx = threadIdx.x, ty = threadIdx.y;  // 32 x 8
    #pragma unroll
    for (int i = 0; i < 32; i += 8)
        tile[ty + i][tx] = in[(size_t)(k0 + ty + i) * N + n0 + tx];
    __syncthreads();
    #pragma unroll
    for (int i = 0; i < 32; i += 8) {
        float v = tile[tx][ty + i];
        oh[(size_t)(n0 + ty + i) * Kd + k0 + tx] = __float2half(v);
    }
}

// conv weights (ho,hi,k) -> [ho][k*1024+hi]
__global__ void wconv_kernel(const float* __restrict__ w, fp16* __restrict__ oh) {
    int ho = blockIdx.x;
    for (int hi = threadIdx.x; hi < 1024; hi += 256) {
        float4 v = *reinterpret_cast<const float4*>(w + ((size_t)ho * 1024 + hi) * 4);
        float vv[4] = {v.x, v.y, v.z, v.w};
        #pragma unroll
        for (int k = 0; k < 4; k++)
            oh[(size_t)ho * 4096 + k * 1024 + hi] = __float2half(vv[k]);
    }
}

// fp32 -> fp16 elementwise
__global__ void fcvt_kernel(const float* __restrict__ in, fp16* __restrict__ oh) {
    size_t i = ((size_t)blockIdx.x * 256 + threadIdx.x) * 4;
    float4 v = *reinterpret_cast<const float4*>(in + i);
    __half2 a = __floats2half2_rn(v.x, v.y);
    __half2 b = __floats2half2_rn(v.z, v.w);
    *reinterpret_cast<__half2*>(oh + i)     = a;
    *reinterpret_cast<__half2*>(oh + i + 2) = b;
}

// ---------------- fp16 HMMA GEMM (cp.async 3-stage + ldmatrix) ----------------
// C[M,N] = A @ B(+bias)(+resid); A: [M][K] fp16 (CONV=1: implicit im2col of x),
// B: [N][K] fp16 (the "col" operand of mma.row.col).
#define ROWB   80                 // padded SMEM row stride: 64B data + 16B pad
#define OPB    (128 * ROWB)       // one operand region per stage = 10240 B
#define STAGEB (2 * OPB)          // A|B = 20480 B
#define NST    3
#define SMEM_TOT (NST * STAGEB)   // 61440 B

#define MMA16816(d, a, b)                                                        \
    asm volatile("mma.sync.aligned.m16n8k16.row.col.f32.f16.f16.f32 "            \
                 "{%0,%1,%2,%3},{%4,%5,%6,%7},{%8,%9},{%0,%1,%2,%3};"            \
                 : "+f"((d)[0]), "+f"((d)[1]), "+f"((d)[2]), "+f"((d)[3])        \
                 : "r"((a)[0]), "r"((a)[1]), "r"((a)[2]), "r"((a)[3]),           \
                   "r"((b)[0]), "r"((b)[1]))

#define LDSM4(r0, r1, r2, r3, addr)                                              \
    asm volatile("ldmatrix.sync.aligned.m8n8.x4.shared.b16 {%0,%1,%2,%3}, [%4];" \
                 : "=r"(r0), "=r"(r1), "=r"(r2), "=r"(r3) : "r"(addr))

#define CPA(dst, src, sz)                                                        \
    asm volatile("cp.async.cg.shared.global [%0], [%1], 16, %2;"                 \
                 :: "r"(dst), "l"(src), "r"(sz) : "memory")

#define CPA_COMMIT() asm volatile("cp.async.commit_group;" ::: "memory")
#define CPA_WAIT1()  asm volatile("cp.async.wait_group 1;" ::: "memory")

template<int CONV>
__global__ void __launch_bounds__(256, 2)
mma_gemm(const fp16* __restrict__ Ah, const fp16* __restrict__ Bh,
         float* __restrict__ C,
         const float* __restrict__ bias, const float* __restrict__ resid,
         int N, int Kd)
{
    extern __shared__ char sm[];
    const uint32_t sb = cvta_s(sm);
    const int tid = threadIdx.x;
    const int wid = tid >> 5, lid = tid & 31;
    const int wm = wid >> 2, wn = wid & 3;         // 2 x 4 warp grid
    const int m0 = blockIdx.y * 128, n0 = blockIdx.x * 128;

    // cp.async: each thread covers rows {tid>>2, 64+(tid>>2)}, 16B chunk (tid&3)
    const int crow = tid >> 2, cc = tid & 3;

    // ldmatrix lane offsets
    const uint32_t aLane = (uint32_t)((lid & 15) * ROWB + (lid >> 4) * 16);
    const uint32_t bLane = (uint32_t)((((lid & 7) + ((lid >> 4) << 3)) * ROWB) +
                                      (((lid >> 3) & 1) * 16));

    float acc[4][4][4];
    #pragma unroll
    for (int i = 0; i < 4; i++)
        #pragma unroll
        for (int j = 0; j < 4; j++)
            #pragma unroll
            for (int q = 0; q < 4; q++) acc[i][j][q] = 0.0f;

    // ---- async tile load into stage slot ----
    #define ISSUE(slot, kg)                                                          \
        {                                                                            \
            uint32_t dbase = sb + (uint32_t)(slot) * STAGEB;                         \
            _Pragma("unroll")                                                        \
            for (int p = 0; p < 2; ++p) {                                            \
                int r = crow + p * 64;                                               \
                uint32_t off = (uint32_t)(r * ROWB + cc * 16);                       \
                size_t bo = (size_t)(n0 + r) * Kd + (kg) + cc * 8;                   \
                CPA(dbase + OPB + off, Bh + bo, 16);                                 \
                if (CONV) {                                                          \
                    int kidx = (kg) >> 10;                                           \
                    bool ok = (((m0 + r) & (Lc - 1)) + kidx) >= 3;                   \
                    size_t ao = (size_t)(m0 + r + kidx - 3) * Hc +                   \
                                ((kg) & 1023) + cc * 8;                              \
                    const fp16* sh = ok ? Ah + ao : Ah;                              \
                    int sz = ok ? 16 : 0;                                            \
                    CPA(dbase + off, sh, sz);                                        \
                } else {                                                             \
                    size_t ao = (size_t)(m0 + r) * Kd + (kg) + cc * 8;               \
                    CPA(dbase + off, Ah + ao, 16);                                   \
                }                                                                    \
            }                                                                        \
        }

    const int T = Kd / 32;
    ISSUE(0, 0); CPA_COMMIT();
    ISSUE(1, 32); CPA_COMMIT();

    int slot = 0;
    for (int t = 0; t < T; ++t) {
        CPA_WAIT1();
        __syncthreads();
        if (t + 2 < T) {
            int ns = slot + 2; if (ns >= NST) ns -= NST;
            ISSUE(ns, (t + 2) * 32);
        }
        CPA_COMMIT();

        const uint32_t base = sb + (uint32_t)slot * STAGEB;
        #pragma unroll
        for (int ks = 0; ks < 2; ++ks) {
            const uint32_t ko = ks * 32;
            uint32_t ah[4][4], bh[4][2];
            #pragma unroll
            for (int i = 0; i < 4; ++i) {
                uint32_t ra = base + (uint32_t)((wm * 64 + i * 16) * ROWB) + aLane + ko;
                LDSM4(ah[i][0], ah[i][1], ah[i][2], ah[i][3], ra);
            }
            #pragma unroll
            for (int jp = 0; jp < 2; ++jp) {
                uint32_t rb = base + OPB +
                              (uint32_t)((wn * 32 + jp * 16) * ROWB) + bLane + ko;
                LDSM4(bh[2 * jp][0], bh[2 * jp][1], bh[2 * jp + 1][0], bh[2 * jp + 1][1], rb);
            }
            #pragma unroll
            for (int i = 0; i < 4; ++i)
                #pragma unroll
                for (int j = 0; j < 4; ++j)
                    MMA16816(acc[i][j], ah[i], bh[j]);
        }
        ++slot; if (slot >= NST) slot = 0;
    }

    // ---- epilogue ----
    const int g = lid >> 2, t4 = lid & 3;
    #pragma unroll
    for (int i = 0; i < 4; ++i) {
        int r0 = m0 + wm * 64 + i * 16 + g;
        #pragma unroll
        for (int j = 0; j < 4; ++j) {
            int ccl = n0 + wn * 32 + j * 8 + 2 * t4;
            float2 v0 = make_float2(acc[i][j][0], acc[i][j][1]);
            float2 v1 = make_float2(acc[i][j][2], acc[i][j][3]);
            if (bias) {
                float2 bb = *reinterpret_cast<const float2*>(bias + ccl);
                v0.x += bb.x; v0.y += bb.y; v1.x += bb.x; v1.y += bb.y;
            }
            if (resid) {
                float2 q0 = *reinterpret_cast<const float2*>(resid + (size_t)r0 * N + ccl);
                float2 q1 = *reinterpret_cast<const float2*>(resid + (size_t)(r0 + 8) * N + ccl);
                v0.x += q0.x; v0.y += q0.y; v1.x += q1.x; v1.y += q1.y;
            }
            *reinterpret_cast<float2*>(C + (size_t)r0 * N + ccl) = v0;
            *reinterpret_cast<float2*>(C + (size_t)(r0 + 8) * N + ccl) = v1;
        }
    }
    #undef ISSUE
}

// ---------------- layernorm over H=1024 (+ fp16 emit) ----------------
__global__ void ln_kernel(const float* __restrict__ in, float* __restrict__ out,
                          fp16* __restrict__ oh,
                          const float* __restrict__ w, const float* __restrict__ b) {
    int t = blockIdx.x, tid = threadIdx.x;
    const float* row = in + (size_t)t * Hc;
    float v[4];
    float s = 0.0f;
    #pragma unroll
    for (int i = 0; i < 4; i++) { v[i] = row[tid + i * 256]; s += v[i]; }
    s = blockReduceSum(s);
    float mean = s * (1.0f / Hc);
    float sq = 0.0f;
    #pragma unroll
    for (int i = 0; i < 4; i++) { float d = v[i] - mean; sq += d * d; }
    sq = blockReduceSum(sq);
    float rstd = rsqrtf(sq * (1.0f / Hc) + 1e-5f);
    #pragma unroll
    for (int i = 0; i < 4; i++) {
        int idx = tid + i * 256;
        float o = (v[i] - mean) * rstd * w[idx] + b[idx];
        out[(size_t)t * Hc + idx] = o;
        oh[(size_t)t * Hc + idx] = __float2half(o);
    }
}

// ---------------- SRU scan + lambda blend (register-pipelined, depth 8) ----------------
#define UNR 8
__global__ void __launch_bounds__(32)
scan_kernel(const float* __restrict__ U, const float* __restrict__ xn,
            const float* __restrict__ cnn, float* __restrict__ blend,
            const float* __restrict__ vf_, const float* __restrict__ vr_,
            const float* __restrict__ bf_, const float* __restrict__ br_,
            const float* __restrict__ lam_, int Bv) {
    int g = blockIdx.x * 32 + threadIdx.x;
    if (g >= Bv * Hc) return;
    int b = g >> 10, h = g & 1023;
    const float vf = vf_[h], vr = vr_[h], bfv = bf_[h], brv = br_[h], lam = lam_[h];
    const float SCALE_X = sqrtf(1.0f + expf(-4.0f));
    size_t iu = ((size_t)b * Lc) * (3 * Hc) + h;
    size_t ix = ((size_t)b * Lc) * Hc + h;

    float bu0[2][UNR], bu1[2][UNR], bu2[2][UNR], bxn[2][UNR], bcn[2][UNR];

    // prefetch block 0
    #pragma unroll
    for (int j = 0; j < UNR; j++) {
        size_t ju = iu + (size_t)j * (3 * Hc);
        size_t jx = ix + (size_t)j * Hc;
        bu0[0][j] = U[ju];
        bu1[0][j] = U[ju + Hc];
        bu2[0][j] = U[ju + 2 * Hc];
        bxn[0][j] = xn[jx];
        bcn[0][j] = cnn[jx];
    }

    float c = 0.0f;
    const int NB = Lc / UNR;
    for (int blk = 0; blk < NB; ++blk) {
        const int cur = blk & 1, nxt = cur ^ 1;
        if (blk + 1 < NB) {
            size_t iu2 = iu + (size_t)UNR * (3 * Hc);
            size_t ix2 = ix + (size_t)UNR * Hc;
            #pragma unroll
            for (int j = 0; j < UNR; j++) {
                size_t ju = iu2 + (size_t)j * (3 * Hc);
                size_t jx = ix2 + (size_t)j * Hc;
                bu0[nxt][j] = U[ju];
                bu1[nxt][j] = U[ju + Hc];
                bu2[nxt][j] = U[ju + 2 * Hc];
                bxn[nxt][j] = xn[jx];
                bcn[nxt][j] = cnn[jx];
            }
        }
        #pragma unroll
        for (int j = 0; j < UNR; j++) {
            float u0 = bu0[cur][j], u1 = bu1[cur][j], u2 = bu2[cur][j];
            float xr = bxn[cur][j] * SCALE_X;
            float cnv = bcn[cur][j];
            float f = 1.0f / (1.0f + __expf(-(fmaf(c, vf, u1) + bfv)));
            float cn = fmaf(f, c - u0, u0);
            float r = 1.0f / (1.0f + __expf(-(fmaf(c, vr, u2) + brv)));
            float th = tanhf(cn);
            float ht = fmaf(r, th - xr, xr);
            blend[ix + (size_t)j * Hc] = fmaf(lam, cnv - ht, ht);
            c = cn;
        }
        iu += (size_t)UNR * (3 * Hc);
        ix += (size_t)UNR * Hc;
    }
}

// ---------------- rmsnorm + gate + ln1 + gelu -> gated(f32), a1 fp16 ----------------
__global__ void rms_gate_ln1_kernel(const float* __restrict__ blend, const float* __restrict__ x,
                                    const float* __restrict__ rmsw,
                                    const float* __restrict__ ln1w, const float* __restrict__ ln1b,
                                    float* __restrict__ gated, fp16* __restrict__ a1h) {
    int t = blockIdx.x, tid = threadIdx.x;
    size_t base = (size_t)t * Hc;
    float v[4], g[4];
    float sq = 0.0f;
    #pragma unroll
    for (int i = 0; i < 4; i++) { v[i] = blend[base + tid + i * 256]; sq += v[i] * v[i]; }
    sq = blockReduceSum(sq);
    float rs = rsqrtf(sq * (1.0f / Hc) + 1e-6f);
    float s = 0.0f;
    #pragma unroll
    for (int i = 0; i < 4; i++) {
        int idx = tid + i * 256;
        float o = rmsw[idx] * v[i] * rs;
        g[i] = o * x[base + idx];
        gated[base + idx] = g[i];
        s += g[i];
    }
    s = blockReduceSum(s);
    float mean = s * (1.0f / Hc);
    float var = 0.0f;
    #pragma unroll
    for (int i = 0; i < 4; i++) { float d = g[i] - mean; var += d * d; }
    var = blockReduceSum(var);
    float rstd = rsqrtf(var * (1.0f / Hc) + 1e-5f);
    #pragma unroll
    for (int i = 0; i < 4; i++) {
        int idx = tid + i * 256;
        float a = geluf((g[i] - mean) * rstd * ln1w[idx] + ln1b[idx]);
        a1h[base + idx] = __float2half(a);
    }
}

// ---------------- ln2 + gelu over 2H -> a2 fp16 ----------------
__global__ void ln2_gelu_kernel(const float* __restrict__ t1, fp16* __restrict__ a2h,
                                const float* __restrict__ w, const float* __restrict__ b) {
    int t = blockIdx.x, tid = threadIdx.x;
    const int NN = 2 * Hc;
    size_t base = (size_t)t * NN;
    float v[8];
    float s = 0.0f;
    #pragma unroll
    for (int i = 0; i < 8; i++) { v[i] = t1[base + tid + i * 256]; s += v[i]; }
    s = blockReduceSum(s);
    float mean = s * (1.0f / NN);
    float sq = 0.0f;
    #pragma unroll
    for (int i = 0; i < 8; i++) { float d = v[i] - mean; sq += d * d; }
    sq = blockReduceSum(sq);
    float rstd = rsqrtf(sq * (1.0f / NN) + 1e-5f);
    #pragma unroll
    for (int i = 0; i < 8; i++) {
        int idx = tid + i * 256;
        float a = geluf((v[i] - mean) * rstd * w[idx] + b[idx]);
        a2h[base + idx] = __float2half(a);
    }
}

// ---------------- launch ----------------
extern "C" void kernel_launch(void* const* d_in, const int* in_sizes, int n_in,
                              void* d_out, int out_size) {
    const float* x        = (const float*)d_in[0];
    const float* conv_w   = (const float*)d_in[1];
    const float* conv_b   = (const float*)d_in[2];
    const float* sru_ln_w = (const float*)d_in[3];
    const float* sru_ln_b = (const float*)d_in[4];
    const float* sru_W    = (const float*)d_in[5];
    const float* sru_vf   = (const float*)d_in[6];
    const float* sru_vr   = (const float*)d_in[7];
    const float* sru_bf   = (const float*)d_in[8];
    const float* sru_br   = (const float*)d_in[9];
    const float* lambda_w = (const float*)d_in[10];
    const float* rms_w    = (const float*)d_in[11];
    const float* ln1_w    = (const float*)d_in[12];
    const float* ln1_b    = (const float*)d_in[13];
    const float* lin1_w   = (const float*)d_in[14];
    const float* ln2_w    = (const float*)d_in[15];
    const float* ln2_b    = (const float*)d_in[16];
    const float* lin2_w   = (const float*)d_in[17];
    const float* lin2_b   = (const float*)d_in[18];

    int Bv = in_sizes[0] / (Lc * Hc);
    int M  = Bv * Lc;

    float *cnn, *xn, *U, *blend, *gated, *t1;
    fp16 *xh, *xnh, *a1h, *a2h, *Wc, *Wu, *W1, *W2;
    cudaGetSymbolAddress((void**)&cnn,   g_cnn);
    cudaGetSymbolAddress((void**)&xn,    g_xn);
    cudaGetSymbolAddress((void**)&U,     g_U);
    cudaGetSymbolAddress((void**)&blend, g_blend);
    cudaGetSymbolAddress((void**)&gated, g_gated);
    cudaGetSymbolAddress((void**)&t1,    g_t1);
    cudaGetSymbolAddress((void**)&xh,  g_xh);
    cudaGetSymbolAddress((void**)&xnh, g_xnh);
    cudaGetSymbolAddress((void**)&a1h, g_a1h);
    cudaGetSymbolAddress((void**)&a2h, g_a2h);
    cudaGetSymbolAddress((void**)&Wc, g_WcT);
    cudaGetSymbolAddress((void**)&Wu, g_WuT);
    cudaGetSymbolAddress((void**)&W1, g_W1T);
    cudaGetSymbolAddress((void**)&W2, g_W2T);

    cudaFuncSetAttribute(mma_gemm<0>, cudaFuncAttributeMaxDynamicSharedMemorySize, SMEM_TOT);
    cudaFuncSetAttribute(mma_gemm<1>, cudaFuncAttributeMaxDynamicSharedMemorySize, SMEM_TOT);

    // weight + input prep
    wconv_kernel<<<1024, 256>>>(conv_w, Wc);
    wtrans_kernel<<<dim3(3072 / 32, 1024 / 32), dim3(32, 8)>>>(sru_W, Wu, 1024, 3072);
    wtrans_kernel<<<dim3(2048 / 32, 1024 / 32), dim3(32, 8)>>>(lin1_w, W1, 1024, 2048);
    wtrans_kernel<<<dim3(1024 / 32, 2048 / 32), dim3(32, 8)>>>(lin2_w, W2, 2048, 1024);
    fcvt_kernel<<<(size_t)M * Hc / 1024, 256>>>(x, xh);

    // 1. causal conv as GEMM
    mma_gemm<1><<<dim3(Hc / 128, M / 128), 256, SMEM_TOT>>>(xh, Wc, cnn, conv_b, nullptr, Hc, 4 * Hc);
    // 2. layernorm (+ fp16 copy)
    ln_kernel<<<M, 256>>>(cnn, xn, xnh, sru_ln_w, sru_ln_b);
    // 3. U = xn @ sru_W
    mma_gemm<0><<<dim3(3 * Hc / 128, M / 128), 256, SMEM_TOT>>>(xnh, Wu, U, nullptr, nullptr, 3 * Hc, Hc);
    // 4. SRU scan + blend (256 blocks x 32 threads, register-pipelined)
    scan_kernel<<<(Bv * Hc + 31) / 32, 32>>>(U, xn, cnn, blend,
                                             sru_vf, sru_vr, sru_bf, sru_br, lambda_w, Bv);
    // 5. rmsnorm + gate + ln1 + gelu
    rms_gate_ln1_kernel<<<M, 256>>>(blend, x, rms_w, ln1_w, ln1_b, gated, a1h);
    // 6. t1 = a1 @ lin1_w
    mma_gemm<0><<<dim3(2 * Hc / 128, M / 128), 256, SMEM_TOT>>>(a1h, W1, t1, nullptr, nullptr, 2 * Hc, Hc);
    // 7. a2 = gelu(ln2(t1))
    ln2_gelu_kernel<<<M, 256>>>(t1, a2h, ln2_w, ln2_b);
    // 8. out = a2 @ lin2_w + lin2_b + gated
    mma_gemm<0><<<dim3(Hc / 128, M / 128), 256, SMEM_TOT>>>(a2h, W2, (float*)d_out, lin2_b, gated, Hc, 2 * Hc);
}